// round 7
// baseline (speedup 1.0000x reference)
#include <cuda_runtime.h>
#include <cuda_bf16.h>
#include <math.h>
#include <stdint.h>

// Problem constants
#define NB 8
#define NS 1024
#define ND 768
#define NH 12
#define NHD 64
#define NM (NB*NS)        // 8192 rows
#define NBH (NB*NH)       // 96 batch-head pairs

// ---------------- scratch (static device globals; no allocation) ----------------
// q/k/v/ctx live as bf16 (half the footprint); proj stays fp32 for LN.
__device__ __nv_bfloat16 g_q  [NM*ND];
__device__ __nv_bfloat16 g_k  [NM*ND];
__device__ __nv_bfloat16 g_v  [NM*ND];
__device__ __nv_bfloat16 g_ctx[NM*ND];
__device__ float         g_proj[NM*ND];

// ---------------- helpers ----------------
__device__ __forceinline__ float warpSum(float v) {
    #pragma unroll
    for (int o = 16; o; o >>= 1) v += __shfl_xor_sync(0xffffffffu, v, o);
    return v;
}
__device__ __forceinline__ float blockSum(float v) {
    __shared__ float s[8];
    __syncthreads();
    v = warpSum(v);
    if ((threadIdx.x & 31) == 0) s[threadIdx.x >> 5] = v;
    __syncthreads();
    if (threadIdx.x == 0) {
        float t = 0.f;
        #pragma unroll
        for (int i = 0; i < 8; i++) t += s[i];
        s[0] = t;
    }
    __syncthreads();
    return s[0];
}

__device__ __forceinline__ void mma_bf16(float d[4], const uint32_t a[4],
                                         const uint32_t b0, const uint32_t b1) {
    asm volatile(
        "mma.sync.aligned.m16n8k16.row.col.f32.bf16.bf16.f32 "
        "{%0,%1,%2,%3}, {%4,%5,%6,%7}, {%8,%9}, {%0,%1,%2,%3};\n"
        : "+f"(d[0]), "+f"(d[1]), "+f"(d[2]), "+f"(d[3])
        : "r"(a[0]), "r"(a[1]), "r"(a[2]), "r"(a[3]),
          "r"(b0), "r"(b1));
}

__device__ __forceinline__ void ldsm_x4(uint32_t r[4], uint32_t saddr) {
    asm volatile("ldmatrix.sync.aligned.m8n8.x4.shared.b16 {%0,%1,%2,%3}, [%4];"
                 : "=r"(r[0]), "=r"(r[1]), "=r"(r[2]), "=r"(r[3]) : "r"(saddr));
}
__device__ __forceinline__ void ldsm_x4_t(uint32_t r[4], uint32_t saddr) {
    asm volatile("ldmatrix.sync.aligned.m8n8.x4.trans.shared.b16 {%0,%1,%2,%3}, [%4];"
                 : "=r"(r[0]), "=r"(r[1]), "=r"(r[2]), "=r"(r[3]) : "r"(saddr));
}

__device__ __forceinline__ uint32_t pack_bf2(float lo, float hi) {
    __nv_bfloat162 p = __floats2bfloat162_rn(lo, hi);   // .x = lo (low halfword)
    return *(uint32_t*)&p;
}

// ---------------- BF16 tensor-core GEMM ----------------
// C[M,768] = A[M,768] @ W[N,768]^T + bias.  BM=BN=128, BK=32 (bf16), 256 thr,
// 8 warps (warpM 0..3, warpN 0..1; warp tile 32x64). Double-buffered.
// SMEM rows: 32 bf16 + 8 pad = 40 halves (80 B); 8-row LDSM groups land on
// distinct 16B bank quads (5r mod 8 distinct).
// ABF: A is bf16 in gmem (no cvt). CBF: C written bf16 (packed), else fp32.
#define GK 768
#define BKH 32           // k per buffer, in halves
#define BSW 20           // smem row stride in 32-bit words (40 halves)
#define ROWB2 80         // smem row stride bytes
#define BUFB2 (128*ROWB2)  // 10240 B per operand buffer

template<bool ABF, bool CBF>
__global__ __launch_bounds__(256)
void bf16_gemm_nt_bias(const void* __restrict__ Ain, const float* __restrict__ W,
                       const float* __restrict__ bias, void* __restrict__ Cout,
                       int M, int N)
{
    extern __shared__ uint32_t sm[];
    // layout: Abuf0 | Abuf1 | Bbuf0 | Bbuf1, each 128*BSW words
    const int t     = threadIdx.x;
    const int warp  = t >> 5;
    const int lane  = t & 31;
    const int warpM = warp >> 1;
    const int warpN = warp & 1;
    const int cRow  = blockIdx.y * 128;
    const int cCol  = blockIdx.x * 128;

    const int ldRow = t >> 1;          // 0..127
    const int ldSeg = t & 1;           // half-row segment (16 halves / 16 floats)

    const float* Wg = W + (long)(cCol + ldRow) * GK + ldSeg * 16;
    const float* Af = ABF ? nullptr : (const float*)Ain + (long)(cRow + ldRow) * GK + ldSeg * 16;
    const __nv_bfloat16* Ab = ABF ? (const __nv_bfloat16*)Ain + (long)(cRow + ldRow) * GK + ldSeg * 16 : nullptr;

    uint32_t* Asm = sm + (long)0;
    uint32_t* Bsm = sm + 2 * 128 * BSW;
    const int sOff = ldRow * BSW + ldSeg * 8;   // word offset of this thread's 8 words

    // ---- fill buffer 0 ----
    {
        // W: fp32 -> bf16
        float4 w0 = *(const float4*)(Wg + 0);
        float4 w1 = *(const float4*)(Wg + 4);
        float4 w2 = *(const float4*)(Wg + 8);
        float4 w3 = *(const float4*)(Wg + 12);
        uint4 u0 = make_uint4(pack_bf2(w0.x,w0.y), pack_bf2(w0.z,w0.w),
                              pack_bf2(w1.x,w1.y), pack_bf2(w1.z,w1.w));
        uint4 u1 = make_uint4(pack_bf2(w2.x,w2.y), pack_bf2(w2.z,w2.w),
                              pack_bf2(w3.x,w3.y), pack_bf2(w3.z,w3.w));
        *(uint4*)&Bsm[sOff]     = u0;
        *(uint4*)&Bsm[sOff + 4] = u1;
        if (ABF) {
            uint4 a0 = *(const uint4*)(Ab + 0);
            uint4 a1 = *(const uint4*)(Ab + 8);
            *(uint4*)&Asm[sOff]     = a0;
            *(uint4*)&Asm[sOff + 4] = a1;
        } else {
            float4 a0 = *(const float4*)(Af + 0);
            float4 a1 = *(const float4*)(Af + 4);
            float4 a2 = *(const float4*)(Af + 8);
            float4 a3 = *(const float4*)(Af + 12);
            uint4 v0 = make_uint4(pack_bf2(a0.x,a0.y), pack_bf2(a0.z,a0.w),
                                  pack_bf2(a1.x,a1.y), pack_bf2(a1.z,a1.w));
            uint4 v1 = make_uint4(pack_bf2(a2.x,a2.y), pack_bf2(a2.z,a2.w),
                                  pack_bf2(a3.x,a3.y), pack_bf2(a3.z,a3.w));
            *(uint4*)&Asm[sOff]     = v0;
            *(uint4*)&Asm[sOff + 4] = v1;
        }
    }
    __syncthreads();

    float acc[2][8][4];
    #pragma unroll
    for (int i = 0; i < 2; i++)
        #pragma unroll
        for (int j = 0; j < 8; j++)
            #pragma unroll
            for (int r = 0; r < 4; r++) acc[i][j][r] = 0.f;

    const int lq = lane >> 2;
    const int lr = lane & 3;

    // ldmatrix per-lane byte offsets (row stride ROWB2)
    const uint32_t sb = (uint32_t)__cvta_generic_to_shared(sm);
    const uint32_t aoff = (uint32_t)((lane & 15) * ROWB2 + ((lane >> 4) << 4));
    const uint32_t boff = (uint32_t)(((lane & 7) + ((lane >> 4) << 3)) * ROWB2
                                     + (((lane >> 3) & 1) << 4));
    const uint32_t aA0 = sb + (uint32_t)(warpM * 32 * ROWB2) + aoff;
    const uint32_t bB0 = sb + 2 * BUFB2 + (uint32_t)(warpN * 64 * ROWB2) + boff;

    int buf = 0;
    for (int kt = 0; kt < GK; kt += BKH) {
        const bool more = (kt + BKH) < GK;
        float4 pw[4];
        float4 pafl[4];
        uint4  pabf[2];
        if (more) {
            pw[0] = *(const float4*)(Wg + kt + BKH + 0);
            pw[1] = *(const float4*)(Wg + kt + BKH + 4);
            pw[2] = *(const float4*)(Wg + kt + BKH + 8);
            pw[3] = *(const float4*)(Wg + kt + BKH + 12);
            if (ABF) {
                pabf[0] = *(const uint4*)(Ab + kt + BKH + 0);
                pabf[1] = *(const uint4*)(Ab + kt + BKH + 8);
            } else {
                pafl[0] = *(const float4*)(Af + kt + BKH + 0);
                pafl[1] = *(const float4*)(Af + kt + BKH + 4);
                pafl[2] = *(const float4*)(Af + kt + BKH + 8);
                pafl[3] = *(const float4*)(Af + kt + BKH + 12);
            }
        }

        const uint32_t ab = aA0 + buf * BUFB2;
        const uint32_t bb0 = bB0 + buf * BUFB2;

        #pragma unroll
        for (int kb = 0; kb < 2; kb++) {
            uint32_t a0[4], a1[4];
            ldsm_x4(a0, ab + kb * 32);
            ldsm_x4(a1, ab + 16 * ROWB2 + kb * 32);
            #pragma unroll
            for (int nt2 = 0; nt2 < 4; nt2++) {
                uint32_t bbr[4];
                ldsm_x4(bbr, bb0 + nt2 * (16 * ROWB2) + kb * 32);
                mma_bf16(acc[0][nt2 * 2],     a0, bbr[0], bbr[1]);
                mma_bf16(acc[0][nt2 * 2 + 1], a0, bbr[2], bbr[3]);
                mma_bf16(acc[1][nt2 * 2],     a1, bbr[0], bbr[1]);
                mma_bf16(acc[1][nt2 * 2 + 1], a1, bbr[2], bbr[3]);
            }
        }

        if (more) {
            uint32_t* Ad = Asm + (buf ^ 1) * 128 * BSW;
            uint32_t* Bd = Bsm + (buf ^ 1) * 128 * BSW;
            uint4 u0 = make_uint4(pack_bf2(pw[0].x,pw[0].y), pack_bf2(pw[0].z,pw[0].w),
                                  pack_bf2(pw[1].x,pw[1].y), pack_bf2(pw[1].z,pw[1].w));
            uint4 u1 = make_uint4(pack_bf2(pw[2].x,pw[2].y), pack_bf2(pw[2].z,pw[2].w),
                                  pack_bf2(pw[3].x,pw[3].y), pack_bf2(pw[3].z,pw[3].w));
            *(uint4*)&Bd[sOff]     = u0;
            *(uint4*)&Bd[sOff + 4] = u1;
            if (ABF) {
                *(uint4*)&Ad[sOff]     = pabf[0];
                *(uint4*)&Ad[sOff + 4] = pabf[1];
            } else {
                uint4 v0 = make_uint4(pack_bf2(pafl[0].x,pafl[0].y), pack_bf2(pafl[0].z,pafl[0].w),
                                      pack_bf2(pafl[1].x,pafl[1].y), pack_bf2(pafl[1].z,pafl[1].w));
                uint4 v1 = make_uint4(pack_bf2(pafl[2].x,pafl[2].y), pack_bf2(pafl[2].z,pafl[2].w),
                                      pack_bf2(pafl[3].x,pafl[3].y), pack_bf2(pafl[3].z,pafl[3].w));
                *(uint4*)&Ad[sOff]     = v0;
                *(uint4*)&Ad[sOff + 4] = v1;
            }
            __syncthreads();
            buf ^= 1;
        }
    }

    // ---- epilogue ----
    #pragma unroll
    for (int nt = 0; nt < 8; nt++) {
        const int col = cCol + warpN * 64 + nt * 8 + lr * 2;
        const float2 bb = *(const float2*)(bias + col);
        #pragma unroll
        for (int mt = 0; mt < 2; mt++) {
            const int row = cRow + warpM * 32 + mt * 16 + lq;
            float c0 = acc[mt][nt][0] + bb.x;
            float c1 = acc[mt][nt][1] + bb.y;
            float c2 = acc[mt][nt][2] + bb.x;
            float c3 = acc[mt][nt][3] + bb.y;
            if (CBF) {
                __nv_bfloat16* Cb = (__nv_bfloat16*)Cout;
                *(uint32_t*)(Cb + (long)row * N + col)       = pack_bf2(c0, c1);
                *(uint32_t*)(Cb + (long)(row + 8) * N + col) = pack_bf2(c2, c3);
            } else {
                float* Cf = (float*)Cout;
                *(float2*)(Cf + (long)row * N + col)       = make_float2(c0, c1);
                *(float2*)(Cf + (long)(row + 8) * N + col) = make_float2(c2, c3);
            }
        }
    }
}

// ---------------- BF16 tensor-core flash attention (bf16 in / bf16 out) ----------------
#define FW 36     // row stride in 32-bit words (72 bf16)
#define ROWB 144  // row stride bytes

__global__ __launch_bounds__(256, 2)
void flash_bf16_kernel(const __nv_bfloat16* __restrict__ Q,
                       const __nv_bfloat16* __restrict__ Kx,
                       const __nv_bfloat16* __restrict__ Vx,
                       const float* __restrict__ mask,
                       const float* __restrict__ head_mask,
                       __nv_bfloat16* __restrict__ Cx)
{
    extern __shared__ uint32_t fsm[];
    uint32_t* Qs = fsm;                 // [128][FW]  Q natural [row][d] bf16
    uint32_t* Ks = Qs + 128 * FW;       // [64][FW]   K natural [key][d] bf16
    uint32_t* Vs = Ks + 64 * FW;        // [64][FW]   V natural [key][d] bf16
    uint32_t* Ps = Vs + 64 * FW;        // [128][FW]  P natural [row][key] bf16
    float*    Ms = (float*)(Ps + 128 * FW);  // [1024] mask row

    const int bh = blockIdx.y;
    const int b  = bh / NH;
    const int h  = bh % NH;
    const int q0 = blockIdx.x * 128;
    const int t  = threadIdx.x;
    const int warp = t >> 5, lane = t & 31;
    const int lq = lane >> 2, lr = lane & 3;
    const int qrow = warp * 16;

    const __nv_bfloat16* Qg = Q  + (long)b * NS * ND + (long)h * NHD;
    const __nv_bfloat16* Kg = Kx + (long)b * NS * ND + (long)h * NHD;
    const __nv_bfloat16* Vg = Vx + (long)b * NS * ND + (long)h * NHD;

    // Load Q tile [128 x 64] (already bf16) + mask row
    {
        const int r = t >> 1;
        const int dbase = (t & 1) * 32;
        #pragma unroll
        for (int i = 0; i < 4; i++) {
            int d0 = dbase + i * 8;
            uint4 qv = *(const uint4*)(Qg + (long)(q0 + r) * ND + d0);
            *(uint4*)&Qs[r * FW + (d0 >> 1)] = qv;
        }
        *(float4*)&Ms[t * 4] = *(const float4*)(mask + b * NS + t * 4);
    }

    // ldmatrix per-lane byte offsets
    const uint32_t sb = (uint32_t)__cvta_generic_to_shared(fsm);
    const uint32_t aoff = (uint32_t)((lane & 15) * ROWB + ((lane >> 4) << 4));
    const uint32_t koff = (uint32_t)(((lane & 7) + ((lane >> 4) << 3)) * ROWB
                                     + (((lane >> 3) & 1) << 4));
    const uint32_t voff = (uint32_t)(((lane & 7) + (((lane >> 3) & 1) << 3)) * ROWB
                                     + ((lane >> 4) << 4));

    const uint32_t qA = sb + (uint32_t)(qrow * ROWB) + aoff;
    const uint32_t kB = sb + (uint32_t)(128 * ROWB) + koff;
    const uint32_t vB = sb + (uint32_t)(192 * ROWB) + voff;
    const uint32_t pA = sb + (uint32_t)((256 + qrow) * ROWB) + aoff;

    float acc_o[8][4];
    #pragma unroll
    for (int nt = 0; nt < 8; nt++)
        #pragma unroll
        for (int j = 0; j < 4; j++) acc_o[nt][j] = 0.f;
    float m0 = -3.4e38f, m1 = -3.4e38f, l0 = 0.f, l1 = 0.f;

    for (int k0 = 0; k0 < NS; k0 += 64) {
        __syncthreads();   // protect Ks/Vs overwrite vs previous tile's reads

        // Load K and V tiles (natural [key][d], already bf16)
        {
            const int r = t >> 2;             // key 0..63
            const int dbase = (t & 3) * 16;
            #pragma unroll
            for (int i = 0; i < 2; i++) {
                int d0 = dbase + i * 8;
                uint4 kv = *(const uint4*)(Kg + (long)(k0 + r) * ND + d0);
                *(uint4*)&Ks[r * FW + (d0 >> 1)] = kv;
                uint4 vv = *(const uint4*)(Vg + (long)(k0 + r) * ND + d0);
                *(uint4*)&Vs[r * FW + (d0 >> 1)] = vv;
            }
        }
        __syncthreads();

        // ---- S = Q @ K^T (16 x 64 per warp), k-dim = d (4 blocks of 16) ----
        float acc_s[8][4];
        #pragma unroll
        for (int nt = 0; nt < 8; nt++)
            #pragma unroll
            for (int j = 0; j < 4; j++) acc_s[nt][j] = 0.f;

        #pragma unroll
        for (int ks = 0; ks < 4; ks++) {
            uint32_t a[4];
            ldsm_x4(a, qA + ks * 32);
            #pragma unroll
            for (int nt2 = 0; nt2 < 4; nt2++) {
                uint32_t bb[4];
                ldsm_x4(bb, kB + nt2 * (16 * ROWB) + ks * 32);
                mma_bf16(acc_s[nt2 * 2],     a, bb[0], bb[1]);
                mma_bf16(acc_s[nt2 * 2 + 1], a, bb[2], bb[3]);
            }
        }

        // ---- scale + mask + online softmax ----
        float mx0 = -3.4e38f, mx1 = -3.4e38f;
        #pragma unroll
        for (int nt = 0; nt < 8; nt++) {
            float2 mk = *(const float2*)&Ms[k0 + nt * 8 + lr * 2];
            acc_s[nt][0] = fmaf(acc_s[nt][0], 0.125f, mk.x);
            acc_s[nt][1] = fmaf(acc_s[nt][1], 0.125f, mk.y);
            acc_s[nt][2] = fmaf(acc_s[nt][2], 0.125f, mk.x);
            acc_s[nt][3] = fmaf(acc_s[nt][3], 0.125f, mk.y);
            mx0 = fmaxf(mx0, fmaxf(acc_s[nt][0], acc_s[nt][1]));
            mx1 = fmaxf(mx1, fmaxf(acc_s[nt][2], acc_s[nt][3]));
        }
        mx0 = fmaxf(mx0, __shfl_xor_sync(0xffffffffu, mx0, 1));
        mx0 = fmaxf(mx0, __shfl_xor_sync(0xffffffffu, mx0, 2));
        mx1 = fmaxf(mx1, __shfl_xor_sync(0xffffffffu, mx1, 1));
        mx1 = fmaxf(mx1, __shfl_xor_sync(0xffffffffu, mx1, 2));

        const float mn0 = fmaxf(m0, mx0);
        const float mn1 = fmaxf(m1, mx1);
        const float corr0 = __expf(m0 - mn0);
        const float corr1 = __expf(m1 - mn1);
        m0 = mn0; m1 = mn1;

        float ls0 = 0.f, ls1 = 0.f;
        #pragma unroll
        for (int nt = 0; nt < 8; nt++) {
            __nv_bfloat162 pb0 = __floats2bfloat162_rn(__expf(acc_s[nt][0] - mn0),
                                                       __expf(acc_s[nt][1] - mn0));
            __nv_bfloat162 pb1 = __floats2bfloat162_rn(__expf(acc_s[nt][2] - mn1),
                                                       __expf(acc_s[nt][3] - mn1));
            ls0 += __bfloat162float(pb0.x) + __bfloat162float(pb0.y);
            ls1 += __bfloat162float(pb1.x) + __bfloat162float(pb1.y);
            Ps[(qrow + lq) * FW + nt * 4 + lr]     = *(uint32_t*)&pb0;
            Ps[(qrow + lq + 8) * FW + nt * 4 + lr] = *(uint32_t*)&pb1;
        }
        ls0 += __shfl_xor_sync(0xffffffffu, ls0, 1);
        ls0 += __shfl_xor_sync(0xffffffffu, ls0, 2);
        ls1 += __shfl_xor_sync(0xffffffffu, ls1, 1);
        ls1 += __shfl_xor_sync(0xffffffffu, ls1, 2);
        l0 = l0 * corr0 + ls0;
        l1 = l1 * corr1 + ls1;

        #pragma unroll
        for (int nt = 0; nt < 8; nt++) {
            acc_o[nt][0] *= corr0;
            acc_o[nt][1] *= corr0;
            acc_o[nt][2] *= corr1;
            acc_o[nt][3] *= corr1;
        }
        __syncwarp();   // Ps STS -> LDSM (cross-lane within warp)

        // ---- O += P @ V, k-dim = key (4 blocks of 16) ----
        #pragma unroll
        for (int kb = 0; kb < 4; kb++) {
            uint32_t a[4];
            ldsm_x4(a, pA + kb * 32);
            #pragma unroll
            for (int nd2 = 0; nd2 < 4; nd2++) {
                uint32_t bb[4];
                ldsm_x4_t(bb, vB + kb * (16 * ROWB) + nd2 * 32);
                mma_bf16(acc_o[nd2 * 2],     a, bb[0], bb[1]);
                mma_bf16(acc_o[nd2 * 2 + 1], a, bb[2], bb[3]);
            }
        }
    }

    // ---- epilogue: normalize, head_mask, write ctx (bf16) ----
    const float hm = head_mask[h];
    const float inv0 = hm / l0;
    const float inv1 = hm / l1;
    #pragma unroll
    for (int nt = 0; nt < 8; nt++) {
        const int col = h * NHD + nt * 8 + lr * 2;
        const long r0 = (long)b * NS + q0 + qrow + lq;
        *(uint32_t*)(Cx + r0 * ND + col) =
            pack_bf2(acc_o[nt][0] * inv0, acc_o[nt][1] * inv0);
        *(uint32_t*)(Cx + (r0 + 8) * ND + col) =
            pack_bf2(acc_o[nt][2] * inv1, acc_o[nt][3] * inv1);
    }
}

// ---------------- residual + LayerNorm ----------------
__global__ __launch_bounds__(256)
void ln_kernel(const float* __restrict__ proj, const float* __restrict__ hidden,
               const float* __restrict__ gamma, const float* __restrict__ beta,
               float* __restrict__ out)
{
    const long row = blockIdx.x;
    const int t = threadIdx.x;
    float x[3];
    #pragma unroll
    for (int k = 0; k < 3; k++) {
        long idx = row * ND + t + k * 256;
        x[k] = proj[idx] + hidden[idx];
    }
    float s = x[0] + x[1] + x[2];
    float mu = blockSum(s) * (1.0f / ND);
    float vs = 0.f;
    #pragma unroll
    for (int k = 0; k < 3; k++) { float d = x[k] - mu; vs += d * d; }
    float var = blockSum(vs) * (1.0f / ND);
    float rstd = rsqrtf(var + 1e-12f);
    #pragma unroll
    for (int k = 0; k < 3; k++) {
        int c = t + k * 256;
        out[row * ND + c] = (x[k] - mu) * rstd * gamma[c] + beta[c];
    }
}

// ---------------- launch ----------------
extern "C" void kernel_launch(void* const* d_in, const int* in_sizes, int n_in,
                              void* d_out, int out_size)
{
    const float* hidden    = (const float*)d_in[0];
    const float* attn_mask = (const float*)d_in[1];
    const float* head_mask = (const float*)d_in[2];
    const float* Wq = (const float*)d_in[3];
    const float* bq = (const float*)d_in[4];
    const float* Wk = (const float*)d_in[5];
    const float* bk = (const float*)d_in[6];
    const float* Wv = (const float*)d_in[7];
    const float* bv = (const float*)d_in[8];
    const float* Wo = (const float*)d_in[9];
    const float* bo = (const float*)d_in[10];
    const float* gamma = (const float*)d_in[11];
    const float* beta  = (const float*)d_in[12];
    float* out = (float*)d_out;

    void *pq, *pk, *pv, *pc, *pp;
    cudaGetSymbolAddress(&pq, g_q);
    cudaGetSymbolAddress(&pk, g_k);
    cudaGetSymbolAddress(&pv, g_v);
    cudaGetSymbolAddress(&pc, g_ctx);
    cudaGetSymbolAddress(&pp, g_proj);
    __nv_bfloat16* q  = (__nv_bfloat16*)pq;
    __nv_bfloat16* k  = (__nv_bfloat16*)pk;
    __nv_bfloat16* v  = (__nv_bfloat16*)pv;
    __nv_bfloat16* cx = (__nv_bfloat16*)pc;
    float* pr = (float*)pp;

    const int FLASH_SMEM = (128*FW + 64*FW + 64*FW + 128*FW) * 4 + 4096;  // 59392 B
    const int GEMM_SMEM  = 4 * 128 * BSW * 4;                             // 40960 B
    static int attr_set = 0;
    if (!attr_set) {
        cudaFuncSetAttribute(flash_bf16_kernel,
                             cudaFuncAttributeMaxDynamicSharedMemorySize, FLASH_SMEM);
        cudaFuncSetAttribute(bf16_gemm_nt_bias<false, true>,
                             cudaFuncAttributeMaxDynamicSharedMemorySize, GEMM_SMEM);
        cudaFuncSetAttribute(bf16_gemm_nt_bias<true, false>,
                             cudaFuncAttributeMaxDynamicSharedMemorySize, GEMM_SMEM);
        attr_set = 1;
    }

    dim3 gGemm(ND / 128, NM / 128);   // (6, 64)
    bf16_gemm_nt_bias<false, true><<<gGemm, 256, GEMM_SMEM>>>(hidden, Wq, bq, q, NM, ND);
    bf16_gemm_nt_bias<false, true><<<gGemm, 256, GEMM_SMEM>>>(hidden, Wk, bk, k, NM, ND);
    bf16_gemm_nt_bias<false, true><<<gGemm, 256, GEMM_SMEM>>>(hidden, Wv, bv, v, NM, ND);

    dim3 gF(NS / 128, NBH);           // (8, 96)
    flash_bf16_kernel<<<gF, 256, FLASH_SMEM>>>(q, k, v, attn_mask, head_mask, cx);

    bf16_gemm_nt_bias<true, false><<<gGemm, 256, GEMM_SMEM>>>(cx, Wo, bo, pr, NM, ND);

    ln_kernel<<<NM, 256>>>(pr, hidden, gamma, beta, out);
}

// round 8
// speedup vs baseline: 1.4556x; 1.4556x over previous
#include <cuda_runtime.h>
#include <cuda_bf16.h>
#include <math.h>
#include <stdint.h>

// Problem constants
#define NB 8
#define NS 1024
#define ND 768
#define NH 12
#define NHD 64
#define NM (NB*NS)        // 8192 rows
#define NBH (NB*NH)       // 96 batch-head pairs

// ---------------- scratch (static device globals; no allocation) ----------------
__device__ __nv_bfloat16 g_q  [NM*ND];
__device__ __nv_bfloat16 g_k  [NM*ND];
__device__ __nv_bfloat16 g_v  [NM*ND];
__device__ __nv_bfloat16 g_ctx[NM*ND];
__device__ float         g_proj[NM*ND];

// ---------------- helpers ----------------
__device__ __forceinline__ float warpSum(float v) {
    #pragma unroll
    for (int o = 16; o; o >>= 1) v += __shfl_xor_sync(0xffffffffu, v, o);
    return v;
}
__device__ __forceinline__ float blockSum(float v) {
    __shared__ float s[8];
    __syncthreads();
    v = warpSum(v);
    if ((threadIdx.x & 31) == 0) s[threadIdx.x >> 5] = v;
    __syncthreads();
    if (threadIdx.x == 0) {
        float t = 0.f;
        #pragma unroll
        for (int i = 0; i < 8; i++) t += s[i];
        s[0] = t;
    }
    __syncthreads();
    return s[0];
}

__device__ __forceinline__ void mma_bf16(float d[4], const uint32_t a[4],
                                         const uint32_t b0, const uint32_t b1) {
    asm volatile(
        "mma.sync.aligned.m16n8k16.row.col.f32.bf16.bf16.f32 "
        "{%0,%1,%2,%3}, {%4,%5,%6,%7}, {%8,%9}, {%0,%1,%2,%3};\n"
        : "+f"(d[0]), "+f"(d[1]), "+f"(d[2]), "+f"(d[3])
        : "r"(a[0]), "r"(a[1]), "r"(a[2]), "r"(a[3]),
          "r"(b0), "r"(b1));
}

__device__ __forceinline__ void ldsm_x4(uint32_t r[4], uint32_t saddr) {
    asm volatile("ldmatrix.sync.aligned.m8n8.x4.shared.b16 {%0,%1,%2,%3}, [%4];"
                 : "=r"(r[0]), "=r"(r[1]), "=r"(r[2]), "=r"(r[3]) : "r"(saddr));
}
__device__ __forceinline__ void ldsm_x4_t(uint32_t r[4], uint32_t saddr) {
    asm volatile("ldmatrix.sync.aligned.m8n8.x4.trans.shared.b16 {%0,%1,%2,%3}, [%4];"
                 : "=r"(r[0]), "=r"(r[1]), "=r"(r[2]), "=r"(r[3]) : "r"(saddr));
}

__device__ __forceinline__ uint32_t pack_bf2(float lo, float hi) {
    __nv_bfloat162 p = __floats2bfloat162_rn(lo, hi);   // .x = lo (low halfword)
    return *(uint32_t*)&p;
}

// ---------------- BF16 tensor-core GEMM, coalesced loaders ----------------
// C[M,768] = A[M,768] @ W[N,768]^T + bias.  BM=BN=128, BK=32 halves, 256 thr,
// 8 warps (warpM 0..3, warpN 0..1; warp tile 32x64). Double-buffered.
// SMEM row stride 20 words (40 halves): LDSM 8-row groups conflict-free
// (5*r mod 8 distinct).
// Loaders (coalesced): W fp32 row=t>>3,col=(t&7)*4 floats (4 passes, warp LDG
// covers 4 full 128B lines); A bf16 row=t>>2,col=(t&3)*8 halves (2 passes).
// NQKV: gridDim.z instances sharing A (QKV fusion). ABF: A bf16. CBF: C bf16.
#define GK 768
#define BKH 32             // k per buffer (halves)
#define BSW 20             // smem row stride in 32-bit words
#define ROWB2 80           // smem row stride bytes
#define BUFB2 (128*ROWB2)  // bytes per operand buffer

template<bool ABF, bool CBF>
__global__ __launch_bounds__(256)
void bf16_gemm_nt_bias(const void* __restrict__ Ain,
                       const float* __restrict__ W0, const float* __restrict__ W1,
                       const float* __restrict__ W2,
                       const float* __restrict__ b0, const float* __restrict__ b1,
                       const float* __restrict__ b2,
                       void* __restrict__ C0, void* __restrict__ C1,
                       void* __restrict__ C2,
                       int M, int N)
{
    extern __shared__ uint32_t sm[];
    // layout: Abuf0 | Abuf1 | Bbuf0 | Bbuf1, each 128*BSW words
    const int z = blockIdx.z;
    const float* W    = (z == 0) ? W0 : (z == 1) ? W1 : W2;
    const float* bias = (z == 0) ? b0 : (z == 1) ? b1 : b2;
    void* Cout        = (z == 0) ? C0 : (z == 1) ? C1 : C2;

    const int t     = threadIdx.x;
    const int warp  = t >> 5;
    const int lane  = t & 31;
    const int warpM = warp >> 1;
    const int warpN = warp & 1;
    const int cRow  = blockIdx.y * 128;
    const int cCol  = blockIdx.x * 128;

    // coalesced loader indices
    const int wRow = t >> 3;           // 0..31 (fp32 rows, 4 passes of 32)
    const int wCol = (t & 7) * 4;      // float col
    const int aRow = t >> 2;           // 0..63 (bf16 rows, 2 passes of 64)
    const int aCol = (t & 3) * 8;      // half col

    const float* Wg = W + (long)(cCol + wRow) * GK + wCol;
    const float* Af = ABF ? nullptr
                          : (const float*)Ain + (long)(cRow + wRow) * GK + wCol;
    const __nv_bfloat16* Ab = ABF
        ? (const __nv_bfloat16*)Ain + (long)(cRow + aRow) * GK + aCol : nullptr;

    uint32_t* Asm = sm;
    uint32_t* Bsm = sm + 2 * 128 * BSW;

    // ---- fill buffer 0 ----
    #pragma unroll
    for (int p = 0; p < 4; p++) {
        float4 w = *(const float4*)(Wg + (long)(p * 32) * GK);
        *(uint2*)&Bsm[(p * 32 + wRow) * BSW + (wCol >> 1)] =
            make_uint2(pack_bf2(w.x, w.y), pack_bf2(w.z, w.w));
    }
    if (ABF) {
        #pragma unroll
        for (int p = 0; p < 2; p++) {
            uint4 a = *(const uint4*)(Ab + (long)(p * 64) * GK);
            *(uint4*)&Asm[(p * 64 + aRow) * BSW + (aCol >> 1)] = a;
        }
    } else {
        #pragma unroll
        for (int p = 0; p < 4; p++) {
            float4 a = *(const float4*)(Af + (long)(p * 32) * GK);
            *(uint2*)&Asm[(p * 32 + wRow) * BSW + (wCol >> 1)] =
                make_uint2(pack_bf2(a.x, a.y), pack_bf2(a.z, a.w));
        }
    }
    __syncthreads();

    float acc[2][8][4];
    #pragma unroll
    for (int i = 0; i < 2; i++)
        #pragma unroll
        for (int j = 0; j < 8; j++)
            #pragma unroll
            for (int r = 0; r < 4; r++) acc[i][j][r] = 0.f;

    const int lq = lane >> 2;
    const int lr = lane & 3;

    // ldmatrix per-lane byte offsets (row stride ROWB2)
    const uint32_t sb = (uint32_t)__cvta_generic_to_shared(sm);
    const uint32_t aoff = (uint32_t)((lane & 15) * ROWB2 + ((lane >> 4) << 4));
    const uint32_t boff = (uint32_t)(((lane & 7) + ((lane >> 4) << 3)) * ROWB2
                                     + (((lane >> 3) & 1) << 4));
    const uint32_t aA0 = sb + (uint32_t)(warpM * 32 * ROWB2) + aoff;
    const uint32_t bB0 = sb + 2 * BUFB2 + (uint32_t)(warpN * 64 * ROWB2) + boff;

    int buf = 0;
    for (int kt = 0; kt < GK; kt += BKH) {
        const bool more = (kt + BKH) < GK;
        float4 pw[4];
        float4 paf[4];
        uint4  pab[2];
        if (more) {
            #pragma unroll
            for (int p = 0; p < 4; p++)
                pw[p] = *(const float4*)(Wg + (long)(p * 32) * GK + kt + BKH);
            if (ABF) {
                #pragma unroll
                for (int p = 0; p < 2; p++)
                    pab[p] = *(const uint4*)(Ab + (long)(p * 64) * GK + kt + BKH);
            } else {
                #pragma unroll
                for (int p = 0; p < 4; p++)
                    paf[p] = *(const float4*)(Af + (long)(p * 32) * GK + kt + BKH);
            }
        }

        const uint32_t ab  = aA0 + buf * BUFB2;
        const uint32_t bb0 = bB0 + buf * BUFB2;

        #pragma unroll
        for (int kb = 0; kb < 2; kb++) {
            uint32_t a0[4], a1[4];
            ldsm_x4(a0, ab + kb * 32);
            ldsm_x4(a1, ab + 16 * ROWB2 + kb * 32);
            #pragma unroll
            for (int nt2 = 0; nt2 < 4; nt2++) {
                uint32_t bbr[4];
                ldsm_x4(bbr, bb0 + nt2 * (16 * ROWB2) + kb * 32);
                mma_bf16(acc[0][nt2 * 2],     a0, bbr[0], bbr[1]);
                mma_bf16(acc[0][nt2 * 2 + 1], a0, bbr[2], bbr[3]);
                mma_bf16(acc[1][nt2 * 2],     a1, bbr[0], bbr[1]);
                mma_bf16(acc[1][nt2 * 2 + 1], a1, bbr[2], bbr[3]);
            }
        }

        if (more) {
            uint32_t* Ad = Asm + (buf ^ 1) * 128 * BSW;
            uint32_t* Bd = Bsm + (buf ^ 1) * 128 * BSW;
            #pragma unroll
            for (int p = 0; p < 4; p++)
                *(uint2*)&Bd[(p * 32 + wRow) * BSW + (wCol >> 1)] =
                    make_uint2(pack_bf2(pw[p].x, pw[p].y), pack_bf2(pw[p].z, pw[p].w));
            if (ABF) {
                #pragma unroll
                for (int p = 0; p < 2; p++)
                    *(uint4*)&Ad[(p * 64 + aRow) * BSW + (aCol >> 1)] = pab[p];
            } else {
                #pragma unroll
                for (int p = 0; p < 4; p++)
                    *(uint2*)&Ad[(p * 32 + wRow) * BSW + (wCol >> 1)] =
                        make_uint2(pack_bf2(paf[p].x, paf[p].y), pack_bf2(paf[p].z, paf[p].w));
            }
            __syncthreads();
            buf ^= 1;
        }
    }

    // ---- epilogue ----
    #pragma unroll
    for (int nt = 0; nt < 8; nt++) {
        const int col = cCol + warpN * 64 + nt * 8 + lr * 2;
        const float2 bb = *(const float2*)(bias + col);
        #pragma unroll
        for (int mt = 0; mt < 2; mt++) {
            const int row = cRow + warpM * 32 + mt * 16 + lq;
            float c0 = acc[mt][nt][0] + bb.x;
            float c1 = acc[mt][nt][1] + bb.y;
            float c2 = acc[mt][nt][2] + bb.x;
            float c3 = acc[mt][nt][3] + bb.y;
            if (CBF) {
                __nv_bfloat16* Cb = (__nv_bfloat16*)Cout;
                *(uint32_t*)(Cb + (long)row * N + col)       = pack_bf2(c0, c1);
                *(uint32_t*)(Cb + (long)(row + 8) * N + col) = pack_bf2(c2, c3);
            } else {
                float* Cf = (float*)Cout;
                *(float2*)(Cf + (long)row * N + col)       = make_float2(c0, c1);
                *(float2*)(Cf + (long)(row + 8) * N + col) = make_float2(c2, c3);
            }
        }
    }
}

// ---------------- BF16 tensor-core flash attention (unchanged from round 7) ----------------
#define FW 36     // row stride in 32-bit words (72 bf16)
#define ROWB 144  // row stride bytes

__global__ __launch_bounds__(256, 2)
void flash_bf16_kernel(const __nv_bfloat16* __restrict__ Q,
                       const __nv_bfloat16* __restrict__ Kx,
                       const __nv_bfloat16* __restrict__ Vx,
                       const float* __restrict__ mask,
                       const float* __restrict__ head_mask,
                       __nv_bfloat16* __restrict__ Cx)
{
    extern __shared__ uint32_t fsm[];
    uint32_t* Qs = fsm;                 // [128][FW]  Q natural [row][d]
    uint32_t* Ks = Qs + 128 * FW;       // [64][FW]   K natural [key][d]
    uint32_t* Vs = Ks + 64 * FW;        // [64][FW]   V natural [key][d]
    uint32_t* Ps = Vs + 64 * FW;        // [128][FW]  P natural [row][key]
    float*    Ms = (float*)(Ps + 128 * FW);  // [1024] mask row

    const int bh = blockIdx.y;
    const int b  = bh / NH;
    const int h  = bh % NH;
    const int q0 = blockIdx.x * 128;
    const int t  = threadIdx.x;
    const int warp = t >> 5, lane = t & 31;
    const int lq = lane >> 2, lr = lane & 3;
    const int qrow = warp * 16;

    const __nv_bfloat16* Qg = Q  + (long)b * NS * ND + (long)h * NHD;
    const __nv_bfloat16* Kg = Kx + (long)b * NS * ND + (long)h * NHD;
    const __nv_bfloat16* Vg = Vx + (long)b * NS * ND + (long)h * NHD;

    {
        const int r = t >> 1;
        const int dbase = (t & 1) * 32;
        #pragma unroll
        for (int i = 0; i < 4; i++) {
            int d0 = dbase + i * 8;
            uint4 qv = *(const uint4*)(Qg + (long)(q0 + r) * ND + d0);
            *(uint4*)&Qs[r * FW + (d0 >> 1)] = qv;
        }
        *(float4*)&Ms[t * 4] = *(const float4*)(mask + b * NS + t * 4);
    }

    const uint32_t sb = (uint32_t)__cvta_generic_to_shared(fsm);
    const uint32_t aoff = (uint32_t)((lane & 15) * ROWB + ((lane >> 4) << 4));
    const uint32_t koff = (uint32_t)(((lane & 7) + ((lane >> 4) << 3)) * ROWB
                                     + (((lane >> 3) & 1) << 4));
    const uint32_t voff = (uint32_t)(((lane & 7) + (((lane >> 3) & 1) << 3)) * ROWB
                                     + ((lane >> 4) << 4));

    const uint32_t qA = sb + (uint32_t)(qrow * ROWB) + aoff;
    const uint32_t kB = sb + (uint32_t)(128 * ROWB) + koff;
    const uint32_t vB = sb + (uint32_t)(192 * ROWB) + voff;
    const uint32_t pA = sb + (uint32_t)((256 + qrow) * ROWB) + aoff;

    float acc_o[8][4];
    #pragma unroll
    for (int nt = 0; nt < 8; nt++)
        #pragma unroll
        for (int j = 0; j < 4; j++) acc_o[nt][j] = 0.f;
    float m0 = -3.4e38f, m1 = -3.4e38f, l0 = 0.f, l1 = 0.f;

    for (int k0 = 0; k0 < NS; k0 += 64) {
        __syncthreads();
        {
            const int r = t >> 2;
            const int dbase = (t & 3) * 16;
            #pragma unroll
            for (int i = 0; i < 2; i++) {
                int d0 = dbase + i * 8;
                uint4 kv = *(const uint4*)(Kg + (long)(k0 + r) * ND + d0);
                *(uint4*)&Ks[r * FW + (d0 >> 1)] = kv;
                uint4 vv = *(const uint4*)(Vg + (long)(k0 + r) * ND + d0);
                *(uint4*)&Vs[r * FW + (d0 >> 1)] = vv;
            }
        }
        __syncthreads();

        float acc_s[8][4];
        #pragma unroll
        for (int nt = 0; nt < 8; nt++)
            #pragma unroll
            for (int j = 0; j < 4; j++) acc_s[nt][j] = 0.f;

        #pragma unroll
        for (int ks = 0; ks < 4; ks++) {
            uint32_t a[4];
            ldsm_x4(a, qA + ks * 32);
            #pragma unroll
            for (int nt2 = 0; nt2 < 4; nt2++) {
                uint32_t bb[4];
                ldsm_x4(bb, kB + nt2 * (16 * ROWB) + ks * 32);
                mma_bf16(acc_s[nt2 * 2],     a, bb[0], bb[1]);
                mma_bf16(acc_s[nt2 * 2 + 1], a, bb[2], bb[3]);
            }
        }

        float mx0 = -3.4e38f, mx1 = -3.4e38f;
        #pragma unroll
        for (int nt = 0; nt < 8; nt++) {
            float2 mk = *(const float2*)&Ms[k0 + nt * 8 + lr * 2];
            acc_s[nt][0] = fmaf(acc_s[nt][0], 0.125f, mk.x);
            acc_s[nt][1] = fmaf(acc_s[nt][1], 0.125f, mk.y);
            acc_s[nt][2] = fmaf(acc_s[nt][2], 0.125f, mk.x);
            acc_s[nt][3] = fmaf(acc_s[nt][3], 0.125f, mk.y);
            mx0 = fmaxf(mx0, fmaxf(acc_s[nt][0], acc_s[nt][1]));
            mx1 = fmaxf(mx1, fmaxf(acc_s[nt][2], acc_s[nt][3]));
        }
        mx0 = fmaxf(mx0, __shfl_xor_sync(0xffffffffu, mx0, 1));
        mx0 = fmaxf(mx0, __shfl_xor_sync(0xffffffffu, mx0, 2));
        mx1 = fmaxf(mx1, __shfl_xor_sync(0xffffffffu, mx1, 1));
        mx1 = fmaxf(mx1, __shfl_xor_sync(0xffffffffu, mx1, 2));

        const float mn0 = fmaxf(m0, mx0);
        const float mn1 = fmaxf(m1, mx1);
        const float corr0 = __expf(m0 - mn0);
        const float corr1 = __expf(m1 - mn1);
        m0 = mn0; m1 = mn1;

        float ls0 = 0.f, ls1 = 0.f;
        #pragma unroll
        for (int nt = 0; nt < 8; nt++) {
            __nv_bfloat162 pb0 = __floats2bfloat162_rn(__expf(acc_s[nt][0] - mn0),
                                                       __expf(acc_s[nt][1] - mn0));
            __nv_bfloat162 pb1 = __floats2bfloat162_rn(__expf(acc_s[nt][2] - mn1),
                                                       __expf(acc_s[nt][3] - mn1));
            ls0 += __bfloat162float(pb0.x) + __bfloat162float(pb0.y);
            ls1 += __bfloat162float(pb1.x) + __bfloat162float(pb1.y);
            Ps[(qrow + lq) * FW + nt * 4 + lr]     = *(uint32_t*)&pb0;
            Ps[(qrow + lq + 8) * FW + nt * 4 + lr] = *(uint32_t*)&pb1;
        }
        ls0 += __shfl_xor_sync(0xffffffffu, ls0, 1);
        ls0 += __shfl_xor_sync(0xffffffffu, ls0, 2);
        ls1 += __shfl_xor_sync(0xffffffffu, ls1, 1);
        ls1 += __shfl_xor_sync(0xffffffffu, ls1, 2);
        l0 = l0 * corr0 + ls0;
        l1 = l1 * corr1 + ls1;

        #pragma unroll
        for (int nt = 0; nt < 8; nt++) {
            acc_o[nt][0] *= corr0;
            acc_o[nt][1] *= corr0;
            acc_o[nt][2] *= corr1;
            acc_o[nt][3] *= corr1;
        }
        __syncwarp();

        #pragma unroll
        for (int kb = 0; kb < 4; kb++) {
            uint32_t a[4];
            ldsm_x4(a, pA + kb * 32);
            #pragma unroll
            for (int nd2 = 0; nd2 < 4; nd2++) {
                uint32_t bb[4];
                ldsm_x4_t(bb, vB + kb * (16 * ROWB) + nd2 * 32);
                mma_bf16(acc_o[nd2 * 2],     a, bb[0], bb[1]);
                mma_bf16(acc_o[nd2 * 2 + 1], a, bb[2], bb[3]);
            }
        }
    }

    const float hm = head_mask[h];
    const float inv0 = hm / l0;
    const float inv1 = hm / l1;
    #pragma unroll
    for (int nt = 0; nt < 8; nt++) {
        const int col = h * NHD + nt * 8 + lr * 2;
        const long r0 = (long)b * NS + q0 + qrow + lq;
        *(uint32_t*)(Cx + r0 * ND + col) =
            pack_bf2(acc_o[nt][0] * inv0, acc_o[nt][1] * inv0);
        *(uint32_t*)(Cx + (r0 + 8) * ND + col) =
            pack_bf2(acc_o[nt][2] * inv1, acc_o[nt][3] * inv1);
    }
}

// ---------------- residual + LayerNorm ----------------
__global__ __launch_bounds__(256)
void ln_kernel(const float* __restrict__ proj, const float* __restrict__ hidden,
               const float* __restrict__ gamma, const float* __restrict__ beta,
               float* __restrict__ out)
{
    const long row = blockIdx.x;
    const int t = threadIdx.x;
    float x[3];
    #pragma unroll
    for (int k = 0; k < 3; k++) {
        long idx = row * ND + t + k * 256;
        x[k] = proj[idx] + hidden[idx];
    }
    float s = x[0] + x[1] + x[2];
    float mu = blockSum(s) * (1.0f / ND);
    float vs = 0.f;
    #pragma unroll
    for (int k = 0; k < 3; k++) { float d = x[k] - mu; vs += d * d; }
    float var = blockSum(vs) * (1.0f / ND);
    float rstd = rsqrtf(var + 1e-12f);
    #pragma unroll
    for (int k = 0; k < 3; k++) {
        int c = t + k * 256;
        out[row * ND + c] = (x[k] - mu) * rstd * gamma[c] + beta[c];
    }
}

// ---------------- launch ----------------
extern "C" void kernel_launch(void* const* d_in, const int* in_sizes, int n_in,
                              void* d_out, int out_size)
{
    const float* hidden    = (const float*)d_in[0];
    const float* attn_mask = (const float*)d_in[1];
    const float* head_mask = (const float*)d_in[2];
    const float* Wq = (const float*)d_in[3];
    const float* bq = (const float*)d_in[4];
    const float* Wk = (const float*)d_in[5];
    const float* bk = (const float*)d_in[6];
    const float* Wv = (const float*)d_in[7];
    const float* bv = (const float*)d_in[8];
    const float* Wo = (const float*)d_in[9];
    const float* bo = (const float*)d_in[10];
    const float* gamma = (const float*)d_in[11];
    const float* beta  = (const float*)d_in[12];
    float* out = (float*)d_out;

    void *pq, *pk, *pv, *pc, *pp;
    cudaGetSymbolAddress(&pq, g_q);
    cudaGetSymbolAddress(&pk, g_k);
    cudaGetSymbolAddress(&pv, g_v);
    cudaGetSymbolAddress(&pc, g_ctx);
    cudaGetSymbolAddress(&pp, g_proj);
    __nv_bfloat16* q  = (__nv_bfloat16*)pq;
    __nv_bfloat16* k  = (__nv_bfloat16*)pk;
    __nv_bfloat16* v  = (__nv_bfloat16*)pv;
    __nv_bfloat16* cx = (__nv_bfloat16*)pc;
    float* pr = (float*)pp;

    const int FLASH_SMEM = (128*FW + 64*FW + 64*FW + 128*FW) * 4 + 4096;  // 59392 B
    const int GEMM_SMEM  = 4 * 128 * BSW * 4;                             // 40960 B
    static int attr_set = 0;
    if (!attr_set) {
        cudaFuncSetAttribute(flash_bf16_kernel,
                             cudaFuncAttributeMaxDynamicSharedMemorySize, FLASH_SMEM);
        cudaFuncSetAttribute(bf16_gemm_nt_bias<false, true>,
                             cudaFuncAttributeMaxDynamicSharedMemorySize, GEMM_SMEM);
        cudaFuncSetAttribute(bf16_gemm_nt_bias<true, false>,
                             cudaFuncAttributeMaxDynamicSharedMemorySize, GEMM_SMEM);
        attr_set = 1;
    }

    // fused QKV: gridDim.z = 3 selects (Wq,bq,q), (Wk,bk,k), (Wv,bv,v)
    dim3 gQKV(ND / 128, NM / 128, 3);   // (6, 64, 3)
    bf16_gemm_nt_bias<false, true><<<gQKV, 256, GEMM_SMEM>>>(
        hidden, Wq, Wk, Wv, bq, bk, bv, q, k, v, NM, ND);

    dim3 gF(NS / 128, NBH);             // (8, 96)
    flash_bf16_kernel<<<gF, 256, FLASH_SMEM>>>(q, k, v, attn_mask, head_mask, cx);

    dim3 gO(ND / 128, NM / 128, 1);     // (6, 64, 1)
    bf16_gemm_nt_bias<true, false><<<gO, 256, GEMM_SMEM>>>(
        cx, Wo, Wo, Wo, bo, bo, bo, pr, pr, pr, NM, ND);

    ln_kernel<<<NM, 256>>>(pr, hidden, gamma, beta, out);
}

// round 10
// speedup vs baseline: 1.5793x; 1.0850x over previous
#include <cuda_runtime.h>
#include <cuda_bf16.h>
#include <math.h>
#include <stdint.h>

// Problem constants
#define NB 8
#define NS 1024
#define ND 768
#define NH 12
#define NHD 64
#define NM (NB*NS)        // 8192 rows
#define NBH (NB*NH)       // 96 batch-head pairs
#define WSZ (ND*ND)       // 589824

// ---------------- scratch (static device globals; no allocation) ----------------
__device__ __nv_bfloat16 g_q  [NM*ND];
__device__ __nv_bfloat16 g_k  [NM*ND];
__device__ __nv_bfloat16 g_v  [NM*ND];
__device__ __nv_bfloat16 g_ctx[NM*ND];
__device__ float         g_proj[NM*ND];
__device__ __nv_bfloat16 g_hid[NM*ND];     // hidden pre-converted to bf16
__device__ __nv_bfloat16 g_wb [4*WSZ];     // Wq|Wk|Wv|Wo pre-converted to bf16

// ---------------- helpers ----------------
__device__ __forceinline__ float warpSum(float v) {
    #pragma unroll
    for (int o = 16; o; o >>= 1) v += __shfl_xor_sync(0xffffffffu, v, o);
    return v;
}
__device__ __forceinline__ float blockSum(float v) {
    __shared__ float s[8];
    __syncthreads();
    v = warpSum(v);
    if ((threadIdx.x & 31) == 0) s[threadIdx.x >> 5] = v;
    __syncthreads();
    if (threadIdx.x == 0) {
        float t = 0.f;
        #pragma unroll
        for (int i = 0; i < 8; i++) t += s[i];
        s[0] = t;
    }
    __syncthreads();
    return s[0];
}

__device__ __forceinline__ void mma_bf16(float d[4], const uint32_t a[4],
                                         const uint32_t b0, const uint32_t b1) {
    asm volatile(
        "mma.sync.aligned.m16n8k16.row.col.f32.bf16.bf16.f32 "
        "{%0,%1,%2,%3}, {%4,%5,%6,%7}, {%8,%9}, {%0,%1,%2,%3};\n"
        : "+f"(d[0]), "+f"(d[1]), "+f"(d[2]), "+f"(d[3])
        : "r"(a[0]), "r"(a[1]), "r"(a[2]), "r"(a[3]),
          "r"(b0), "r"(b1));
}

__device__ __forceinline__ void ldsm_x4(uint32_t r[4], uint32_t saddr) {
    asm volatile("ldmatrix.sync.aligned.m8n8.x4.shared.b16 {%0,%1,%2,%3}, [%4];"
                 : "=r"(r[0]), "=r"(r[1]), "=r"(r[2]), "=r"(r[3]) : "r"(saddr));
}
__device__ __forceinline__ void ldsm_x4_t(uint32_t r[4], uint32_t saddr) {
    asm volatile("ldmatrix.sync.aligned.m8n8.x4.trans.shared.b16 {%0,%1,%2,%3}, [%4];"
                 : "=r"(r[0]), "=r"(r[1]), "=r"(r[2]), "=r"(r[3]) : "r"(saddr));
}

__device__ __forceinline__ uint32_t pack_bf2(float lo, float hi) {
    __nv_bfloat162 p = __floats2bfloat162_rn(lo, hi);   // .x = lo (low halfword)
    return *(uint32_t*)&p;
}

// ---------------- fp32 -> bf16 conversion kernels ----------------
__global__ __launch_bounds__(256)
void cvt_hid_kernel(const float* __restrict__ src, __nv_bfloat16* __restrict__ dst) {
    const long i = ((long)blockIdx.x * 256 + threadIdx.x) * 4;
    float4 v = *(const float4*)(src + i);
    *(uint2*)(dst + i) = make_uint2(pack_bf2(v.x, v.y), pack_bf2(v.z, v.w));
}
__global__ __launch_bounds__(256)
void cvt_w_kernel(const float* __restrict__ W0, const float* __restrict__ W1,
                  const float* __restrict__ W2, const float* __restrict__ W3,
                  __nv_bfloat16* __restrict__ dst) {
    const int z = blockIdx.z;
    const float* src = (z == 0) ? W0 : (z == 1) ? W1 : (z == 2) ? W2 : W3;
    const long i = ((long)blockIdx.x * 256 + threadIdx.x) * 4;
    float4 v = *(const float4*)(src + i);
    *(uint2*)(dst + (long)z * WSZ + i) =
        make_uint2(pack_bf2(v.x, v.y), pack_bf2(v.z, v.w));
}

// ---------------- BF16 GEMM, double-buffered sync loads (proven structure) ---
// C[M,768] = A[M,768] @ W[N,768]^T + bias. A,W bf16 in gmem (pre-converted).
// BM=BN=128, BK=32 halves, 256 thr, 8 warps (warp tile 32x64), 2-buffer smem.
// Row stride 40 halves (80B): LDSM 8-row groups conflict-free (5r mod 8).
// Loader: row=t>>2 (2 passes of 64 rows), col=(t&3)*16 bytes — pure uint4 copy.
// gridDim.z selects (bias, C); W = Wbase + z*wstride (QKV fusion).
#define GK 768
#define BKH 32             // k per buffer (halves)
#define BSW 20             // smem row stride in 32-bit words
#define ROWB2 80           // smem row stride bytes
#define BUFB2 (128*ROWB2)  // 10240 B per operand per buffer

template<bool CBF>
__global__ __launch_bounds__(256, 2)
void bf16_gemm_db(const __nv_bfloat16* __restrict__ A,
                  const __nv_bfloat16* __restrict__ Wbase, long wstride,
                  const float* __restrict__ b0, const float* __restrict__ b1,
                  const float* __restrict__ b2,
                  void* __restrict__ C0, void* __restrict__ C1,
                  void* __restrict__ C2, int N)
{
    extern __shared__ uint32_t sm[];
    // layout: Abuf0 | Abuf1 | Bbuf0 | Bbuf1, each 128*BSW words
    const int z = blockIdx.z;
    const float* bias = (z == 0) ? b0 : (z == 1) ? b1 : b2;
    void* Cout        = (z == 0) ? C0 : (z == 1) ? C1 : C2;
    const __nv_bfloat16* W = Wbase + (long)z * wstride;

    const int t     = threadIdx.x;
    const int warp  = t >> 5;
    const int lane  = t & 31;
    const int warpM = warp >> 1;
    const int warpN = warp & 1;
    const int cRow  = blockIdx.y * 128;
    const int cCol  = blockIdx.x * 128;

    // loader: row = t>>2 (0..63, 2 passes), col bytes = (t&3)*16
    const int aRow  = t >> 2;
    const int aColB = (t & 3) * 16;
    const int sOffW = aRow * BSW + (aColB >> 2);   // word offset inside a buffer

    const char* Ag = (const char*)(A + (long)(cRow + aRow) * GK) + aColB;
    const char* Wg = (const char*)(W + (long)(cCol + aRow) * GK) + aColB;
    const long ROWSTEP = (long)64 * GK * 2;        // 64 rows in bytes

    uint32_t* Asm = sm;                      // 2 buffers: [0, 2*128*BSW)
    uint32_t* Bsm = sm + 2 * 128 * BSW;      // 2 buffers

    // ---- fill buffer 0 ----
    {
        uint4 a0 = *(const uint4*)(Ag);
        uint4 a1 = *(const uint4*)(Ag + ROWSTEP);
        uint4 w0 = *(const uint4*)(Wg);
        uint4 w1 = *(const uint4*)(Wg + ROWSTEP);
        *(uint4*)&Asm[sOffW]            = a0;
        *(uint4*)&Asm[sOffW + 64 * BSW] = a1;
        *(uint4*)&Bsm[sOffW]            = w0;
        *(uint4*)&Bsm[sOffW + 64 * BSW] = w1;
    }
    __syncthreads();

    float acc[2][8][4];
    #pragma unroll
    for (int i = 0; i < 2; i++)
        #pragma unroll
        for (int j = 0; j < 8; j++)
            #pragma unroll
            for (int r = 0; r < 4; r++) acc[i][j][r] = 0.f;

    const int lq = lane >> 2;
    const int lr = lane & 3;

    // ldmatrix per-lane byte offsets (row stride ROWB2)
    const uint32_t sb = (uint32_t)__cvta_generic_to_shared(sm);
    const uint32_t aoff = (uint32_t)((lane & 15) * ROWB2 + ((lane >> 4) << 4));
    const uint32_t boff = (uint32_t)(((lane & 7) + ((lane >> 4) << 3)) * ROWB2
                                     + (((lane >> 3) & 1) << 4));
    const uint32_t aA0 = sb + (uint32_t)(warpM * 32 * ROWB2) + aoff;
    const uint32_t bB0 = sb + 2 * BUFB2 + (uint32_t)(warpN * 64 * ROWB2) + boff;

    int buf = 0;
    for (int kt = 0; kt < GK; kt += BKH) {
        const bool more = (kt + BKH) < GK;
        uint4 pa0, pa1, pw0, pw1;
        if (more) {
            const long gk = (long)(kt + BKH) * 2;
            pa0 = *(const uint4*)(Ag + gk);
            pa1 = *(const uint4*)(Ag + gk + ROWSTEP);
            pw0 = *(const uint4*)(Wg + gk);
            pw1 = *(const uint4*)(Wg + gk + ROWSTEP);
        }

        const uint32_t ab  = aA0 + buf * BUFB2;
        const uint32_t bb0 = bB0 + buf * BUFB2;

        #pragma unroll
        for (int kb = 0; kb < 2; kb++) {
            uint32_t a0[4], a1[4];
            ldsm_x4(a0, ab + kb * 32);
            ldsm_x4(a1, ab + 16 * ROWB2 + kb * 32);
            #pragma unroll
            for (int nt2 = 0; nt2 < 4; nt2++) {
                uint32_t bbr[4];
                ldsm_x4(bbr, bb0 + nt2 * (16 * ROWB2) + kb * 32);
                mma_bf16(acc[0][nt2 * 2],     a0, bbr[0], bbr[1]);
                mma_bf16(acc[0][nt2 * 2 + 1], a0, bbr[2], bbr[3]);
                mma_bf16(acc[1][nt2 * 2],     a1, bbr[0], bbr[1]);
                mma_bf16(acc[1][nt2 * 2 + 1], a1, bbr[2], bbr[3]);
            }
        }

        if (more) {
            uint32_t* Ad = Asm + (buf ^ 1) * 128 * BSW;
            uint32_t* Bd = Bsm + (buf ^ 1) * 128 * BSW;
            *(uint4*)&Ad[sOffW]            = pa0;
            *(uint4*)&Ad[sOffW + 64 * BSW] = pa1;
            *(uint4*)&Bd[sOffW]            = pw0;
            *(uint4*)&Bd[sOffW + 64 * BSW] = pw1;
            __syncthreads();
            buf ^= 1;
        }
    }

    // ---- epilogue ----
    #pragma unroll
    for (int nt = 0; nt < 8; nt++) {
        const int col = cCol + warpN * 64 + nt * 8 + lr * 2;
        const float2 bb = *(const float2*)(bias + col);
        #pragma unroll
        for (int mt = 0; mt < 2; mt++) {
            const int row = cRow + warpM * 32 + mt * 16 + lq;
            float c0 = acc[mt][nt][0] + bb.x;
            float c1 = acc[mt][nt][1] + bb.y;
            float c2 = acc[mt][nt][2] + bb.x;
            float c3 = acc[mt][nt][3] + bb.y;
            if (CBF) {
                __nv_bfloat16* Cb = (__nv_bfloat16*)Cout;
                *(uint32_t*)(Cb + (long)row * N + col)       = pack_bf2(c0, c1);
                *(uint32_t*)(Cb + (long)(row + 8) * N + col) = pack_bf2(c2, c3);
            } else {
                float* Cf = (float*)Cout;
                *(float2*)(Cf + (long)row * N + col)       = make_float2(c0, c1);
                *(float2*)(Cf + (long)(row + 8) * N + col) = make_float2(c2, c3);
            }
        }
    }
}

// ---------------- BF16 tensor-core flash attention (unchanged from round 8) ----------------
#define FW 36     // row stride in 32-bit words (72 bf16)
#define ROWB 144  // row stride bytes

__global__ __launch_bounds__(256, 2)
void flash_bf16_kernel(const __nv_bfloat16* __restrict__ Q,
                       const __nv_bfloat16* __restrict__ Kx,
                       const __nv_bfloat16* __restrict__ Vx,
                       const float* __restrict__ mask,
                       const float* __restrict__ head_mask,
                       __nv_bfloat16* __restrict__ Cx)
{
    extern __shared__ uint32_t fsm[];
    uint32_t* Qs = fsm;                 // [128][FW]  Q natural [row][d]
    uint32_t* Ks = Qs + 128 * FW;       // [64][FW]   K natural [key][d]
    uint32_t* Vs = Ks + 64 * FW;        // [64][FW]   V natural [key][d]
    uint32_t* Ps = Vs + 64 * FW;        // [128][FW]  P natural [row][key]
    float*    Ms = (float*)(Ps + 128 * FW);  // [1024] mask row

    const int bh = blockIdx.y;
    const int b  = bh / NH;
    const int h  = bh % NH;
    const int q0 = blockIdx.x * 128;
    const int t  = threadIdx.x;
    const int warp = t >> 5, lane = t & 31;
    const int lq = lane >> 2, lr = lane & 3;
    const int qrow = warp * 16;

    const __nv_bfloat16* Qg = Q  + (long)b * NS * ND + (long)h * NHD;
    const __nv_bfloat16* Kg = Kx + (long)b * NS * ND + (long)h * NHD;
    const __nv_bfloat16* Vg = Vx + (long)b * NS * ND + (long)h * NHD;

    {
        const int r = t >> 1;
        const int dbase = (t & 1) * 32;
        #pragma unroll
        for (int i = 0; i < 4; i++) {
            int d0 = dbase + i * 8;
            uint4 qv = *(const uint4*)(Qg + (long)(q0 + r) * ND + d0);
            *(uint4*)&Qs[r * FW + (d0 >> 1)] = qv;
        }
        *(float4*)&Ms[t * 4] = *(const float4*)(mask + b * NS + t * 4);
    }

    const uint32_t sb = (uint32_t)__cvta_generic_to_shared(fsm);
    const uint32_t aoff = (uint32_t)((lane & 15) * ROWB + ((lane >> 4) << 4));
    const uint32_t koff = (uint32_t)(((lane & 7) + ((lane >> 4) << 3)) * ROWB
                                     + (((lane >> 3) & 1) << 4));
    const uint32_t voff = (uint32_t)(((lane & 7) + (((lane >> 3) & 1) << 3)) * ROWB
                                     + ((lane >> 4) << 4));

    const uint32_t qA = sb + (uint32_t)(qrow * ROWB) + aoff;
    const uint32_t kB = sb + (uint32_t)(128 * ROWB) + koff;
    const uint32_t vB = sb + (uint32_t)(192 * ROWB) + voff;
    const uint32_t pA = sb + (uint32_t)((256 + qrow) * ROWB) + aoff;

    float acc_o[8][4];
    #pragma unroll
    for (int nt = 0; nt < 8; nt++)
        #pragma unroll
        for (int j = 0; j < 4; j++) acc_o[nt][j] = 0.f;
    float m0 = -3.4e38f, m1 = -3.4e38f, l0 = 0.f, l1 = 0.f;

    for (int k0 = 0; k0 < NS; k0 += 64) {
        __syncthreads();
        {
            const int r = t >> 2;
            const int dbase = (t & 3) * 16;
            #pragma unroll
            for (int i = 0; i < 2; i++) {
                int d0 = dbase + i * 8;
                uint4 kv = *(const uint4*)(Kg + (long)(k0 + r) * ND + d0);
                *(uint4*)&Ks[r * FW + (d0 >> 1)] = kv;
                uint4 vv = *(const uint4*)(Vg + (long)(k0 + r) * ND + d0);
                *(uint4*)&Vs[r * FW + (d0 >> 1)] = vv;
            }
        }
        __syncthreads();

        float acc_s[8][4];
        #pragma unroll
        for (int nt = 0; nt < 8; nt++)
            #pragma unroll
            for (int j = 0; j < 4; j++) acc_s[nt][j] = 0.f;

        #pragma unroll
        for (int ks = 0; ks < 4; ks++) {
            uint32_t a[4];
            ldsm_x4(a, qA + ks * 32);
            #pragma unroll
            for (int nt2 = 0; nt2 < 4; nt2++) {
                uint32_t bb[4];
                ldsm_x4(bb, kB + nt2 * (16 * ROWB) + ks * 32);
                mma_bf16(acc_s[nt2 * 2],     a, bb[0], bb[1]);
                mma_bf16(acc_s[nt2 * 2 + 1], a, bb[2], bb[3]);
            }
        }

        float mx0 = -3.4e38f, mx1 = -3.4e38f;
        #pragma unroll
        for (int nt = 0; nt < 8; nt++) {
            float2 mk = *(const float2*)&Ms[k0 + nt * 8 + lr * 2];
            acc_s[nt][0] = fmaf(acc_s[nt][0], 0.125f, mk.x);
            acc_s[nt][1] = fmaf(acc_s[nt][1], 0.125f, mk.y);
            acc_s[nt][2] = fmaf(acc_s[nt][2], 0.125f, mk.x);
            acc_s[nt][3] = fmaf(acc_s[nt][3], 0.125f, mk.y);
            mx0 = fmaxf(mx0, fmaxf(acc_s[nt][0], acc_s[nt][1]));
            mx1 = fmaxf(mx1, fmaxf(acc_s[nt][2], acc_s[nt][3]));
        }
        mx0 = fmaxf(mx0, __shfl_xor_sync(0xffffffffu, mx0, 1));
        mx0 = fmaxf(mx0, __shfl_xor_sync(0xffffffffu, mx0, 2));
        mx1 = fmaxf(mx1, __shfl_xor_sync(0xffffffffu, mx1, 1));
        mx1 = fmaxf(mx1, __shfl_xor_sync(0xffffffffu, mx1, 2));

        const float mn0 = fmaxf(m0, mx0);
        const float mn1 = fmaxf(m1, mx1);
        const float corr0 = __expf(m0 - mn0);
        const float corr1 = __expf(m1 - mn1);
        m0 = mn0; m1 = mn1;

        float ls0 = 0.f, ls1 = 0.f;
        #pragma unroll
        for (int nt = 0; nt < 8; nt++) {
            __nv_bfloat162 pb0 = __floats2bfloat162_rn(__expf(acc_s[nt][0] - mn0),
                                                       __expf(acc_s[nt][1] - mn0));
            __nv_bfloat162 pb1 = __floats2bfloat162_rn(__expf(acc_s[nt][2] - mn1),
                                                       __expf(acc_s[nt][3] - mn1));
            ls0 += __bfloat162float(pb0.x) + __bfloat162float(pb0.y);
            ls1 += __bfloat162float(pb1.x) + __bfloat162float(pb1.y);
            Ps[(qrow + lq) * FW + nt * 4 + lr]     = *(uint32_t*)&pb0;
            Ps[(qrow + lq + 8) * FW + nt * 4 + lr] = *(uint32_t*)&pb1;
        }
        ls0 += __shfl_xor_sync(0xffffffffu, ls0, 1);
        ls0 += __shfl_xor_sync(0xffffffffu, ls0, 2);
        ls1 += __shfl_xor_sync(0xffffffffu, ls1, 1);
        ls1 += __shfl_xor_sync(0xffffffffu, ls1, 2);
        l0 = l0 * corr0 + ls0;
        l1 = l1 * corr1 + ls1;

        #pragma unroll
        for (int nt = 0; nt < 8; nt++) {
            acc_o[nt][0] *= corr0;
            acc_o[nt][1] *= corr0;
            acc_o[nt][2] *= corr1;
            acc_o[nt][3] *= corr1;
        }
        __syncwarp();

        #pragma unroll
        for (int kb = 0; kb < 4; kb++) {
            uint32_t a[4];
            ldsm_x4(a, pA + kb * 32);
            #pragma unroll
            for (int nd2 = 0; nd2 < 4; nd2++) {
                uint32_t bb[4];
                ldsm_x4_t(bb, vB + kb * (16 * ROWB) + nd2 * 32);
                mma_bf16(acc_o[nd2 * 2],     a, bb[0], bb[1]);
                mma_bf16(acc_o[nd2 * 2 + 1], a, bb[2], bb[3]);
            }
        }
    }

    const float hm = head_mask[h];
    const float inv0 = hm / l0;
    const float inv1 = hm / l1;
    #pragma unroll
    for (int nt = 0; nt < 8; nt++) {
        const int col = h * NHD + nt * 8 + lr * 2;
        const long r0 = (long)b * NS + q0 + qrow + lq;
        *(uint32_t*)(Cx + r0 * ND + col) =
            pack_bf2(acc_o[nt][0] * inv0, acc_o[nt][1] * inv0);
        *(uint32_t*)(Cx + (r0 + 8) * ND + col) =
            pack_bf2(acc_o[nt][2] * inv1, acc_o[nt][3] * inv1);
    }
}

// ---------------- residual + LayerNorm ----------------
__global__ __launch_bounds__(256)
void ln_kernel(const float* __restrict__ proj, const float* __restrict__ hidden,
               const float* __restrict__ gamma, const float* __restrict__ beta,
               float* __restrict__ out)
{
    const long row = blockIdx.x;
    const int t = threadIdx.x;
    float x[3];
    #pragma unroll
    for (int k = 0; k < 3; k++) {
        long idx = row * ND + t + k * 256;
        x[k] = proj[idx] + hidden[idx];
    }
    float s = x[0] + x[1] + x[2];
    float mu = blockSum(s) * (1.0f / ND);
    float vs = 0.f;
    #pragma unroll
    for (int k = 0; k < 3; k++) { float d = x[k] - mu; vs += d * d; }
    float var = blockSum(vs) * (1.0f / ND);
    float rstd = rsqrtf(var + 1e-12f);
    #pragma unroll
    for (int k = 0; k < 3; k++) {
        int c = t + k * 256;
        out[row * ND + c] = (x[k] - mu) * rstd * gamma[c] + beta[c];
    }
}

// ---------------- launch ----------------
extern "C" void kernel_launch(void* const* d_in, const int* in_sizes, int n_in,
                              void* d_out, int out_size)
{
    const float* hidden    = (const float*)d_in[0];
    const float* attn_mask = (const float*)d_in[1];
    const float* head_mask = (const float*)d_in[2];
    const float* Wq = (const float*)d_in[3];
    const float* bq = (const float*)d_in[4];
    const float* Wk = (const float*)d_in[5];
    const float* bk = (const float*)d_in[6];
    const float* Wv = (const float*)d_in[7];
    const float* bv = (const float*)d_in[8];
    const float* Wo = (const float*)d_in[9];
    const float* bo = (const float*)d_in[10];
    const float* gamma = (const float*)d_in[11];
    const float* beta  = (const float*)d_in[12];
    float* out = (float*)d_out;

    void *pq, *pk, *pv, *pc, *pp, *ph, *pw;
    cudaGetSymbolAddress(&pq, g_q);
    cudaGetSymbolAddress(&pk, g_k);
    cudaGetSymbolAddress(&pv, g_v);
    cudaGetSymbolAddress(&pc, g_ctx);
    cudaGetSymbolAddress(&pp, g_proj);
    cudaGetSymbolAddress(&ph, g_hid);
    cudaGetSymbolAddress(&pw, g_wb);
    __nv_bfloat16* q   = (__nv_bfloat16*)pq;
    __nv_bfloat16* k   = (__nv_bfloat16*)pk;
    __nv_bfloat16* v   = (__nv_bfloat16*)pv;
    __nv_bfloat16* cx  = (__nv_bfloat16*)pc;
    float*         pr  = (float*)pp;
    __nv_bfloat16* hb  = (__nv_bfloat16*)ph;
    __nv_bfloat16* wb  = (__nv_bfloat16*)pw;

    const int FLASH_SMEM = (128*FW + 64*FW + 64*FW + 128*FW) * 4 + 4096;  // 59392 B
    const int GEMM_SMEM  = 4 * 128 * BSW * 4;                             // 40960 B
    static int attr_set = 0;
    if (!attr_set) {
        cudaFuncSetAttribute(flash_bf16_kernel,
                             cudaFuncAttributeMaxDynamicSharedMemorySize, FLASH_SMEM);
        cudaFuncSetAttribute(bf16_gemm_db<true>,
                             cudaFuncAttributeMaxDynamicSharedMemorySize, GEMM_SMEM);
        cudaFuncSetAttribute(bf16_gemm_db<false>,
                             cudaFuncAttributeMaxDynamicSharedMemorySize, GEMM_SMEM);
        attr_set = 1;
    }

    // pre-convert hidden + weights to bf16
    cvt_hid_kernel<<<NM * ND / 4 / 256, 256>>>(hidden, hb);
    dim3 gW(WSZ / 4 / 256, 1, 4);   // (576,1,4)
    cvt_w_kernel<<<gW, 256>>>(Wq, Wk, Wv, Wo, wb);

    // fused QKV: gridDim.z = 3 selects (Wq,bq,q), (Wk,bk,k), (Wv,bv,v)
    dim3 gQKV(ND / 128, NM / 128, 3);   // (6, 64, 3)
    bf16_gemm_db<true><<<gQKV, 256, GEMM_SMEM>>>(
        hb, wb, (long)WSZ, bq, bk, bv, q, k, v, ND);

    dim3 gF(NS / 128, NBH);             // (8, 96)
    flash_bf16_kernel<<<gF, 256, FLASH_SMEM>>>(q, k, v, attn_mask, head_mask, cx);

    dim3 gO(ND / 128, NM / 128, 1);     // (6, 64, 1)
    bf16_gemm_db<false><<<gO, 256, GEMM_SMEM>>>(
        cx, wb + 3 * WSZ, 0L, bo, bo, bo, pr, pr, pr, ND);

    ln_kernel<<<NM, 256>>>(pr, hidden, gamma, beta, out);
}

// round 11
// speedup vs baseline: 1.6235x; 1.0280x over previous
#include <cuda_runtime.h>
#include <cuda_bf16.h>
#include <math.h>
#include <stdint.h>

// Problem constants
#define NB 8
#define NS 1024
#define ND 768
#define NH 12
#define NHD 64
#define NM (NB*NS)        // 8192 rows
#define NBH (NB*NH)       // 96 batch-head pairs
#define WSZ (ND*ND)       // 589824

// ---------------- scratch (static device globals; no allocation) ----------------
__device__ __nv_bfloat16 g_q  [NM*ND];
__device__ __nv_bfloat16 g_k  [NM*ND];
__device__ __nv_bfloat16 g_v  [NM*ND];
__device__ __nv_bfloat16 g_ctx[NM*ND];
__device__ float         g_proj[NM*ND];
__device__ __nv_bfloat16 g_hid[NM*ND];     // hidden pre-converted to bf16
__device__ __nv_bfloat16 g_wb [4*WSZ];     // Wq|Wk|Wv|Wo pre-converted to bf16

// ---------------- helpers ----------------
__device__ __forceinline__ float warpSum(float v) {
    #pragma unroll
    for (int o = 16; o; o >>= 1) v += __shfl_xor_sync(0xffffffffu, v, o);
    return v;
}
__device__ __forceinline__ float blockSum(float v) {
    __shared__ float s[8];
    __syncthreads();
    v = warpSum(v);
    if ((threadIdx.x & 31) == 0) s[threadIdx.x >> 5] = v;
    __syncthreads();
    if (threadIdx.x == 0) {
        float t = 0.f;
        #pragma unroll
        for (int i = 0; i < 8; i++) t += s[i];
        s[0] = t;
    }
    __syncthreads();
    return s[0];
}

__device__ __forceinline__ void mma_bf16(float d[4], const uint32_t a[4],
                                         const uint32_t b0, const uint32_t b1) {
    asm volatile(
        "mma.sync.aligned.m16n8k16.row.col.f32.bf16.bf16.f32 "
        "{%0,%1,%2,%3}, {%4,%5,%6,%7}, {%8,%9}, {%0,%1,%2,%3};\n"
        : "+f"(d[0]), "+f"(d[1]), "+f"(d[2]), "+f"(d[3])
        : "r"(a[0]), "r"(a[1]), "r"(a[2]), "r"(a[3]),
          "r"(b0), "r"(b1));
}

__device__ __forceinline__ void ldsm_x4(uint32_t r[4], uint32_t saddr) {
    asm volatile("ldmatrix.sync.aligned.m8n8.x4.shared.b16 {%0,%1,%2,%3}, [%4];"
                 : "=r"(r[0]), "=r"(r[1]), "=r"(r[2]), "=r"(r[3]) : "r"(saddr));
}
__device__ __forceinline__ void ldsm_x4_t(uint32_t r[4], uint32_t saddr) {
    asm volatile("ldmatrix.sync.aligned.m8n8.x4.trans.shared.b16 {%0,%1,%2,%3}, [%4];"
                 : "=r"(r[0]), "=r"(r[1]), "=r"(r[2]), "=r"(r[3]) : "r"(saddr));
}

__device__ __forceinline__ uint32_t pack_bf2(float lo, float hi) {
    __nv_bfloat162 p = __floats2bfloat162_rn(lo, hi);   // .x = lo (low halfword)
    return *(uint32_t*)&p;
}

// ---------------- fp32 -> bf16 conversion kernels ----------------
__global__ __launch_bounds__(256)
void cvt_hid_kernel(const float* __restrict__ src, __nv_bfloat16* __restrict__ dst) {
    const long i = ((long)blockIdx.x * 256 + threadIdx.x) * 4;
    float4 v = *(const float4*)(src + i);
    *(uint2*)(dst + i) = make_uint2(pack_bf2(v.x, v.y), pack_bf2(v.z, v.w));
}
__global__ __launch_bounds__(256)
void cvt_w_kernel(const float* __restrict__ W0, const float* __restrict__ W1,
                  const float* __restrict__ W2, const float* __restrict__ W3,
                  __nv_bfloat16* __restrict__ dst) {
    const int z = blockIdx.z;
    const float* src = (z == 0) ? W0 : (z == 1) ? W1 : (z == 2) ? W2 : W3;
    const long i = ((long)blockIdx.x * 256 + threadIdx.x) * 4;
    float4 v = *(const float4*)(src + i);
    *(uint2*)(dst + (long)z * WSZ + i) =
        make_uint2(pack_bf2(v.x, v.y), pack_bf2(v.z, v.w));
}

// ---------------- BF16 GEMM, double-buffered (unchanged from round 10) ------
#define GK 768
#define BKH 32             // k per buffer (halves)
#define BSW 20             // smem row stride in 32-bit words
#define ROWB2 80           // smem row stride bytes
#define BUFB2 (128*ROWB2)  // 10240 B per operand per buffer

template<bool CBF>
__global__ __launch_bounds__(256, 2)
void bf16_gemm_db(const __nv_bfloat16* __restrict__ A,
                  const __nv_bfloat16* __restrict__ Wbase, long wstride,
                  const float* __restrict__ b0, const float* __restrict__ b1,
                  const float* __restrict__ b2,
                  void* __restrict__ C0, void* __restrict__ C1,
                  void* __restrict__ C2, int N)
{
    extern __shared__ uint32_t sm[];
    const int z = blockIdx.z;
    const float* bias = (z == 0) ? b0 : (z == 1) ? b1 : b2;
    void* Cout        = (z == 0) ? C0 : (z == 1) ? C1 : C2;
    const __nv_bfloat16* W = Wbase + (long)z * wstride;

    const int t     = threadIdx.x;
    const int warp  = t >> 5;
    const int lane  = t & 31;
    const int warpM = warp >> 1;
    const int warpN = warp & 1;
    const int cRow  = blockIdx.y * 128;
    const int cCol  = blockIdx.x * 128;

    const int aRow  = t >> 2;
    const int aColB = (t & 3) * 16;
    const int sOffW = aRow * BSW + (aColB >> 2);

    const char* Ag = (const char*)(A + (long)(cRow + aRow) * GK) + aColB;
    const char* Wg = (const char*)(W + (long)(cCol + aRow) * GK) + aColB;
    const long ROWSTEP = (long)64 * GK * 2;

    uint32_t* Asm = sm;
    uint32_t* Bsm = sm + 2 * 128 * BSW;

    {
        uint4 a0 = *(const uint4*)(Ag);
        uint4 a1 = *(const uint4*)(Ag + ROWSTEP);
        uint4 w0 = *(const uint4*)(Wg);
        uint4 w1 = *(const uint4*)(Wg + ROWSTEP);
        *(uint4*)&Asm[sOffW]            = a0;
        *(uint4*)&Asm[sOffW + 64 * BSW] = a1;
        *(uint4*)&Bsm[sOffW]            = w0;
        *(uint4*)&Bsm[sOffW + 64 * BSW] = w1;
    }
    __syncthreads();

    float acc[2][8][4];
    #pragma unroll
    for (int i = 0; i < 2; i++)
        #pragma unroll
        for (int j = 0; j < 8; j++)
            #pragma unroll
            for (int r = 0; r < 4; r++) acc[i][j][r] = 0.f;

    const int lq = lane >> 2;
    const int lr = lane & 3;

    const uint32_t sb = (uint32_t)__cvta_generic_to_shared(sm);
    const uint32_t aoff = (uint32_t)((lane & 15) * ROWB2 + ((lane >> 4) << 4));
    const uint32_t boff = (uint32_t)(((lane & 7) + ((lane >> 4) << 3)) * ROWB2
                                     + (((lane >> 3) & 1) << 4));
    const uint32_t aA0 = sb + (uint32_t)(warpM * 32 * ROWB2) + aoff;
    const uint32_t bB0 = sb + 2 * BUFB2 + (uint32_t)(warpN * 64 * ROWB2) + boff;

    int buf = 0;
    for (int kt = 0; kt < GK; kt += BKH) {
        const bool more = (kt + BKH) < GK;
        uint4 pa0, pa1, pw0, pw1;
        if (more) {
            const long gk = (long)(kt + BKH) * 2;
            pa0 = *(const uint4*)(Ag + gk);
            pa1 = *(const uint4*)(Ag + gk + ROWSTEP);
            pw0 = *(const uint4*)(Wg + gk);
            pw1 = *(const uint4*)(Wg + gk + ROWSTEP);
        }

        const uint32_t ab  = aA0 + buf * BUFB2;
        const uint32_t bb0 = bB0 + buf * BUFB2;

        #pragma unroll
        for (int kb = 0; kb < 2; kb++) {
            uint32_t a0[4], a1[4];
            ldsm_x4(a0, ab + kb * 32);
            ldsm_x4(a1, ab + 16 * ROWB2 + kb * 32);
            #pragma unroll
            for (int nt2 = 0; nt2 < 4; nt2++) {
                uint32_t bbr[4];
                ldsm_x4(bbr, bb0 + nt2 * (16 * ROWB2) + kb * 32);
                mma_bf16(acc[0][nt2 * 2],     a0, bbr[0], bbr[1]);
                mma_bf16(acc[0][nt2 * 2 + 1], a0, bbr[2], bbr[3]);
                mma_bf16(acc[1][nt2 * 2],     a1, bbr[0], bbr[1]);
                mma_bf16(acc[1][nt2 * 2 + 1], a1, bbr[2], bbr[3]);
            }
        }

        if (more) {
            uint32_t* Ad = Asm + (buf ^ 1) * 128 * BSW;
            uint32_t* Bd = Bsm + (buf ^ 1) * 128 * BSW;
            *(uint4*)&Ad[sOffW]            = pa0;
            *(uint4*)&Ad[sOffW + 64 * BSW] = pa1;
            *(uint4*)&Bd[sOffW]            = pw0;
            *(uint4*)&Bd[sOffW + 64 * BSW] = pw1;
            __syncthreads();
            buf ^= 1;
        }
    }

    #pragma unroll
    for (int nt = 0; nt < 8; nt++) {
        const int col = cCol + warpN * 64 + nt * 8 + lr * 2;
        const float2 bb = *(const float2*)(bias + col);
        #pragma unroll
        for (int mt = 0; mt < 2; mt++) {
            const int row = cRow + warpM * 32 + mt * 16 + lq;
            float c0 = acc[mt][nt][0] + bb.x;
            float c1 = acc[mt][nt][1] + bb.y;
            float c2 = acc[mt][nt][2] + bb.x;
            float c3 = acc[mt][nt][3] + bb.y;
            if (CBF) {
                __nv_bfloat16* Cb = (__nv_bfloat16*)Cout;
                *(uint32_t*)(Cb + (long)row * N + col)       = pack_bf2(c0, c1);
                *(uint32_t*)(Cb + (long)(row + 8) * N + col) = pack_bf2(c2, c3);
            } else {
                float* Cf = (float*)Cout;
                *(float2*)(Cf + (long)row * N + col)       = make_float2(c0, c1);
                *(float2*)(Cf + (long)(row + 8) * N + col) = make_float2(c2, c3);
            }
        }
    }
}

// ---------------- BF16 flash attention v2: 4 warps x 32 q-rows -------------
// 128 threads; warp w owns q-rows [32w, 32w+32) as two 16-row m-tiles.
// Q fragments cached in registers across all kv-tiles (loop-invariant).
// Per warp per kv-tile: 16 K-LDSM + 8 P-LDSM + 16 V-LDSM for 128 MMA.
#define FW 36     // row stride in 32-bit words (72 bf16)
#define ROWB 144  // row stride bytes

__global__ __launch_bounds__(128, 2)
void flash_bf16_kernel(const __nv_bfloat16* __restrict__ Q,
                       const __nv_bfloat16* __restrict__ Kx,
                       const __nv_bfloat16* __restrict__ Vx,
                       const float* __restrict__ mask,
                       const float* __restrict__ head_mask,
                       __nv_bfloat16* __restrict__ Cx)
{
    extern __shared__ uint32_t fsm[];
    // rows: Qs[0..127] | Ks[128..191] | Vs[192..255] | Ps[256..383]
    float* Ms = (float*)(fsm + 384 * FW);    // [1024] mask row

    const int bh = blockIdx.y;
    const int b  = bh / NH;
    const int h  = bh % NH;
    const int q0 = blockIdx.x * 128;
    const int t  = threadIdx.x;
    const int warp = t >> 5, lane = t & 31;
    const int lq = lane >> 2, lr = lane & 3;
    const int qrow = warp * 32;

    const __nv_bfloat16* Qg = Q  + (long)b * NS * ND + (long)h * NHD;
    const __nv_bfloat16* Kg = Kx + (long)b * NS * ND + (long)h * NHD;
    const __nv_bfloat16* Vg = Vx + (long)b * NS * ND + (long)h * NHD;

    // Load Q tile [128 rows x 128 B] coalesced: 8 threads per row, 8 passes
    {
        const int seg = t & 7;           // 16B segment in row
        const int rb  = t >> 3;          // 0..15
        #pragma unroll
        for (int i = 0; i < 8; i++) {
            const int r = i * 16 + rb;
            uint4 qv = *(const uint4*)((const char*)(Qg + (long)(q0 + r) * ND) + seg * 16);
            *(uint4*)((char*)fsm + r * ROWB + seg * 16) = qv;
        }
        *(float4*)&Ms[t * 8]     = *(const float4*)(mask + b * NS + t * 8);
        *(float4*)&Ms[t * 8 + 4] = *(const float4*)(mask + b * NS + t * 8 + 4);
    }
    __syncthreads();

    // ldmatrix per-lane byte offsets
    const uint32_t sb = (uint32_t)__cvta_generic_to_shared(fsm);
    const uint32_t aoff = (uint32_t)((lane & 15) * ROWB + ((lane >> 4) << 4));
    const uint32_t koff = (uint32_t)(((lane & 7) + ((lane >> 4) << 3)) * ROWB
                                     + (((lane >> 3) & 1) << 4));
    const uint32_t voff = (uint32_t)(((lane & 7) + (((lane >> 3) & 1) << 3)) * ROWB
                                     + ((lane >> 4) << 4));

    const uint32_t qA = sb + (uint32_t)(qrow * ROWB) + aoff;
    const uint32_t kB = sb + (uint32_t)(128 * ROWB) + koff;
    const uint32_t vB = sb + (uint32_t)(192 * ROWB) + voff;
    const uint32_t pA = sb + (uint32_t)((256 + qrow) * ROWB) + aoff;

    // Cache Q fragments (loop-invariant): 2 m-tiles x 4 k-blocks x 4 regs
    uint32_t qf[2][4][4];
    #pragma unroll
    for (int mt = 0; mt < 2; mt++)
        #pragma unroll
        for (int ks = 0; ks < 4; ks++)
            ldsm_x4(qf[mt][ks], qA + mt * (16 * ROWB) + ks * 32);

    float acc_o[2][8][4];
    #pragma unroll
    for (int mt = 0; mt < 2; mt++)
        #pragma unroll
        for (int nt = 0; nt < 8; nt++)
            #pragma unroll
            for (int j = 0; j < 4; j++) acc_o[mt][nt][j] = 0.f;
    float m[4], l[4];
    #pragma unroll
    for (int i = 0; i < 4; i++) { m[i] = -3.4e38f; l[i] = 0.f; }

    for (int k0 = 0; k0 < NS; k0 += 64) {
        __syncthreads();   // protect Ks/Vs overwrite vs previous tile's reads

        // Load K and V tiles [64 rows x 128 B]: 8 thr/row, 4 passes each
        {
            const int seg = t & 7;
            const int rb  = t >> 3;      // 0..15
            #pragma unroll
            for (int i = 0; i < 4; i++) {
                const int r = i * 16 + rb;
                uint4 kv = *(const uint4*)((const char*)(Kg + (long)(k0 + r) * ND) + seg * 16);
                *(uint4*)((char*)fsm + (128 + r) * ROWB + seg * 16) = kv;
                uint4 vv = *(const uint4*)((const char*)(Vg + (long)(k0 + r) * ND) + seg * 16);
                *(uint4*)((char*)fsm + (192 + r) * ROWB + seg * 16) = vv;
            }
        }
        __syncthreads();

        // ---- S = Q @ K^T (32 x 64 per warp) ----
        float acc_s[2][8][4];
        #pragma unroll
        for (int mt = 0; mt < 2; mt++)
            #pragma unroll
            for (int nt = 0; nt < 8; nt++)
                #pragma unroll
                for (int j = 0; j < 4; j++) acc_s[mt][nt][j] = 0.f;

        #pragma unroll
        for (int ks = 0; ks < 4; ks++) {
            #pragma unroll
            for (int nt2 = 0; nt2 < 4; nt2++) {
                uint32_t bb[4];
                ldsm_x4(bb, kB + nt2 * (16 * ROWB) + ks * 32);
                mma_bf16(acc_s[0][nt2 * 2],     qf[0][ks], bb[0], bb[1]);
                mma_bf16(acc_s[0][nt2 * 2 + 1], qf[0][ks], bb[2], bb[3]);
                mma_bf16(acc_s[1][nt2 * 2],     qf[1][ks], bb[0], bb[1]);
                mma_bf16(acc_s[1][nt2 * 2 + 1], qf[1][ks], bb[2], bb[3]);
            }
        }

        // ---- scale + mask + online softmax (per m-tile) ----
        #pragma unroll
        for (int mt = 0; mt < 2; mt++) {
            float mx0 = -3.4e38f, mx1 = -3.4e38f;
            #pragma unroll
            for (int nt = 0; nt < 8; nt++) {
                float2 mk = *(const float2*)&Ms[k0 + nt * 8 + lr * 2];
                acc_s[mt][nt][0] = fmaf(acc_s[mt][nt][0], 0.125f, mk.x);
                acc_s[mt][nt][1] = fmaf(acc_s[mt][nt][1], 0.125f, mk.y);
                acc_s[mt][nt][2] = fmaf(acc_s[mt][nt][2], 0.125f, mk.x);
                acc_s[mt][nt][3] = fmaf(acc_s[mt][nt][3], 0.125f, mk.y);
                mx0 = fmaxf(mx0, fmaxf(acc_s[mt][nt][0], acc_s[mt][nt][1]));
                mx1 = fmaxf(mx1, fmaxf(acc_s[mt][nt][2], acc_s[mt][nt][3]));
            }
            mx0 = fmaxf(mx0, __shfl_xor_sync(0xffffffffu, mx0, 1));
            mx0 = fmaxf(mx0, __shfl_xor_sync(0xffffffffu, mx0, 2));
            mx1 = fmaxf(mx1, __shfl_xor_sync(0xffffffffu, mx1, 1));
            mx1 = fmaxf(mx1, __shfl_xor_sync(0xffffffffu, mx1, 2));

            const float mn0 = fmaxf(m[mt * 2 + 0], mx0);
            const float mn1 = fmaxf(m[mt * 2 + 1], mx1);
            const float corr0 = __expf(m[mt * 2 + 0] - mn0);
            const float corr1 = __expf(m[mt * 2 + 1] - mn1);
            m[mt * 2 + 0] = mn0;
            m[mt * 2 + 1] = mn1;

            float ls0 = 0.f, ls1 = 0.f;
            #pragma unroll
            for (int nt = 0; nt < 8; nt++) {
                __nv_bfloat162 pb0 = __floats2bfloat162_rn(__expf(acc_s[mt][nt][0] - mn0),
                                                           __expf(acc_s[mt][nt][1] - mn0));
                __nv_bfloat162 pb1 = __floats2bfloat162_rn(__expf(acc_s[mt][nt][2] - mn1),
                                                           __expf(acc_s[mt][nt][3] - mn1));
                ls0 += __bfloat162float(pb0.x) + __bfloat162float(pb0.y);
                ls1 += __bfloat162float(pb1.x) + __bfloat162float(pb1.y);
                fsm[(256 + qrow + mt * 16 + lq) * FW + nt * 4 + lr]     = *(uint32_t*)&pb0;
                fsm[(256 + qrow + mt * 16 + lq + 8) * FW + nt * 4 + lr] = *(uint32_t*)&pb1;
            }
            ls0 += __shfl_xor_sync(0xffffffffu, ls0, 1);
            ls0 += __shfl_xor_sync(0xffffffffu, ls0, 2);
            ls1 += __shfl_xor_sync(0xffffffffu, ls1, 1);
            ls1 += __shfl_xor_sync(0xffffffffu, ls1, 2);
            l[mt * 2 + 0] = l[mt * 2 + 0] * corr0 + ls0;
            l[mt * 2 + 1] = l[mt * 2 + 1] * corr1 + ls1;

            #pragma unroll
            for (int nt = 0; nt < 8; nt++) {
                acc_o[mt][nt][0] *= corr0;
                acc_o[mt][nt][1] *= corr0;
                acc_o[mt][nt][2] *= corr1;
                acc_o[mt][nt][3] *= corr1;
            }
        }
        __syncwarp();   // Ps STS -> LDSM (cross-lane within warp)

        // ---- O += P @ V, k-dim = key (4 blocks of 16) ----
        #pragma unroll
        for (int kb = 0; kb < 4; kb++) {
            uint32_t pa0[4], pa1[4];
            ldsm_x4(pa0, pA + kb * 32);
            ldsm_x4(pa1, pA + 16 * ROWB + kb * 32);
            #pragma unroll
            for (int nd2 = 0; nd2 < 4; nd2++) {
                uint32_t bb[4];
                ldsm_x4_t(bb, vB + kb * (16 * ROWB) + nd2 * 32);
                mma_bf16(acc_o[0][nd2 * 2],     pa0, bb[0], bb[1]);
                mma_bf16(acc_o[0][nd2 * 2 + 1], pa0, bb[2], bb[3]);
                mma_bf16(acc_o[1][nd2 * 2],     pa1, bb[0], bb[1]);
                mma_bf16(acc_o[1][nd2 * 2 + 1], pa1, bb[2], bb[3]);
            }
        }
    }

    // ---- epilogue: normalize, head_mask, write ctx (bf16) ----
    const float hm = head_mask[h];
    #pragma unroll
    for (int mt = 0; mt < 2; mt++) {
        const float inv0 = hm / l[mt * 2 + 0];
        const float inv1 = hm / l[mt * 2 + 1];
        #pragma unroll
        for (int nt = 0; nt < 8; nt++) {
            const int col = h * NHD + nt * 8 + lr * 2;
            const long r0 = (long)b * NS + q0 + qrow + mt * 16 + lq;
            *(uint32_t*)(Cx + r0 * ND + col) =
                pack_bf2(acc_o[mt][nt][0] * inv0, acc_o[mt][nt][1] * inv0);
            *(uint32_t*)(Cx + (r0 + 8) * ND + col) =
                pack_bf2(acc_o[mt][nt][2] * inv1, acc_o[mt][nt][3] * inv1);
        }
    }
}

// ---------------- residual + LayerNorm ----------------
__global__ __launch_bounds__(256)
void ln_kernel(const float* __restrict__ proj, const float* __restrict__ hidden,
               const float* __restrict__ gamma, const float* __restrict__ beta,
               float* __restrict__ out)
{
    const long row = blockIdx.x;
    const int t = threadIdx.x;
    float x[3];
    #pragma unroll
    for (int k = 0; k < 3; k++) {
        long idx = row * ND + t + k * 256;
        x[k] = proj[idx] + hidden[idx];
    }
    float s = x[0] + x[1] + x[2];
    float mu = blockSum(s) * (1.0f / ND);
    float vs = 0.f;
    #pragma unroll
    for (int k = 0; k < 3; k++) { float d = x[k] - mu; vs += d * d; }
    float var = blockSum(vs) * (1.0f / ND);
    float rstd = rsqrtf(var + 1e-12f);
    #pragma unroll
    for (int k = 0; k < 3; k++) {
        int c = t + k * 256;
        out[row * ND + c] = (x[k] - mu) * rstd * gamma[c] + beta[c];
    }
}

// ---------------- launch ----------------
extern "C" void kernel_launch(void* const* d_in, const int* in_sizes, int n_in,
                              void* d_out, int out_size)
{
    const float* hidden    = (const float*)d_in[0];
    const float* attn_mask = (const float*)d_in[1];
    const float* head_mask = (const float*)d_in[2];
    const float* Wq = (const float*)d_in[3];
    const float* bq = (const float*)d_in[4];
    const float* Wk = (const float*)d_in[5];
    const float* bk = (const float*)d_in[6];
    const float* Wv = (const float*)d_in[7];
    const float* bv = (const float*)d_in[8];
    const float* Wo = (const float*)d_in[9];
    const float* bo = (const float*)d_in[10];
    const float* gamma = (const float*)d_in[11];
    const float* beta  = (const float*)d_in[12];
    float* out = (float*)d_out;

    void *pq, *pk, *pv, *pc, *pp, *ph, *pw;
    cudaGetSymbolAddress(&pq, g_q);
    cudaGetSymbolAddress(&pk, g_k);
    cudaGetSymbolAddress(&pv, g_v);
    cudaGetSymbolAddress(&pc, g_ctx);
    cudaGetSymbolAddress(&pp, g_proj);
    cudaGetSymbolAddress(&ph, g_hid);
    cudaGetSymbolAddress(&pw, g_wb);
    __nv_bfloat16* q   = (__nv_bfloat16*)pq;
    __nv_bfloat16* k   = (__nv_bfloat16*)pk;
    __nv_bfloat16* v   = (__nv_bfloat16*)pv;
    __nv_bfloat16* cx  = (__nv_bfloat16*)pc;
    float*         pr  = (float*)pp;
    __nv_bfloat16* hb  = (__nv_bfloat16*)ph;
    __nv_bfloat16* wb  = (__nv_bfloat16*)pw;

    const int FLASH_SMEM = 384 * FW * 4 + 4096;   // 59392 B
    const int GEMM_SMEM  = 4 * 128 * BSW * 4;     // 40960 B
    static int attr_set = 0;
    if (!attr_set) {
        cudaFuncSetAttribute(flash_bf16_kernel,
                             cudaFuncAttributeMaxDynamicSharedMemorySize, FLASH_SMEM);
        cudaFuncSetAttribute(bf16_gemm_db<true>,
                             cudaFuncAttributeMaxDynamicSharedMemorySize, GEMM_SMEM);
        cudaFuncSetAttribute(bf16_gemm_db<false>,
                             cudaFuncAttributeMaxDynamicSharedMemorySize, GEMM_SMEM);
        attr_set = 1;
    }

    // pre-convert hidden + weights to bf16
    cvt_hid_kernel<<<NM * ND / 4 / 256, 256>>>(hidden, hb);
    dim3 gW(WSZ / 4 / 256, 1, 4);   // (576,1,4)
    cvt_w_kernel<<<gW, 256>>>(Wq, Wk, Wv, Wo, wb);

    // fused QKV: gridDim.z = 3 selects (Wq,bq,q), (Wk,bk,k), (Wv,bv,v)
    dim3 gQKV(ND / 128, NM / 128, 3);   // (6, 64, 3)
    bf16_gemm_db<true><<<gQKV, 256, GEMM_SMEM>>>(
        hb, wb, (long)WSZ, bq, bk, bv, q, k, v, ND);

    dim3 gF(NS / 128, NBH);             // (8, 96)
    flash_bf16_kernel<<<gF, 128, FLASH_SMEM>>>(q, k, v, attn_mask, head_mask, cx);

    dim3 gO(ND / 128, NM / 128, 1);     // (6, 64, 1)
    bf16_gemm_db<false><<<gO, 256, GEMM_SMEM>>>(
        cx, wb + 3 * WSZ, 0L, bo, bo, bo, pr, pr, pr, ND);

    ln_kernel<<<NM, 256>>>(pr, hidden, gamma, beta, out);
}

// round 12
// speedup vs baseline: 1.8473x; 1.1378x over previous
#include <cuda_runtime.h>
#include <cuda_bf16.h>
#include <math.h>
#include <stdint.h>

// Problem constants
#define NB 8
#define NS 1024
#define ND 768
#define NH 12
#define NHD 64
#define NM (NB*NS)        // 8192 rows
#define NBH (NB*NH)       // 96 batch-head pairs
#define WSZ (ND*ND)       // 589824

// ---------------- scratch (static device globals; no allocation) ----------------
__device__ __nv_bfloat16 g_q  [NM*ND];
__device__ __nv_bfloat16 g_k  [NM*ND];
__device__ __nv_bfloat16 g_v  [NM*ND];
__device__ __nv_bfloat16 g_ctx[NM*ND];
__device__ float         g_proj[NM*ND];
__device__ __nv_bfloat16 g_hid[NM*ND];     // hidden pre-converted to bf16
__device__ __nv_bfloat16 g_wb [4*WSZ];     // Wq|Wk|Wv|Wo pre-converted to bf16

// ---------------- helpers ----------------
__device__ __forceinline__ float warpSum(float v) {
    #pragma unroll
    for (int o = 16; o; o >>= 1) v += __shfl_xor_sync(0xffffffffu, v, o);
    return v;
}
__device__ __forceinline__ float blockSum(float v) {
    __shared__ float s[8];
    __syncthreads();
    v = warpSum(v);
    if ((threadIdx.x & 31) == 0) s[threadIdx.x >> 5] = v;
    __syncthreads();
    if (threadIdx.x == 0) {
        float t = 0.f;
        #pragma unroll
        for (int i = 0; i < 8; i++) t += s[i];
        s[0] = t;
    }
    __syncthreads();
    return s[0];
}

__device__ __forceinline__ void mma_bf16(float d[4], const uint32_t a[4],
                                         const uint32_t b0, const uint32_t b1) {
    asm volatile(
        "mma.sync.aligned.m16n8k16.row.col.f32.bf16.bf16.f32 "
        "{%0,%1,%2,%3}, {%4,%5,%6,%7}, {%8,%9}, {%0,%1,%2,%3};\n"
        : "+f"(d[0]), "+f"(d[1]), "+f"(d[2]), "+f"(d[3])
        : "r"(a[0]), "r"(a[1]), "r"(a[2]), "r"(a[3]),
          "r"(b0), "r"(b1));
}

__device__ __forceinline__ void ldsm_x4(uint32_t r[4], uint32_t saddr) {
    asm volatile("ldmatrix.sync.aligned.m8n8.x4.shared.b16 {%0,%1,%2,%3}, [%4];"
                 : "=r"(r[0]), "=r"(r[1]), "=r"(r[2]), "=r"(r[3]) : "r"(saddr));
}
__device__ __forceinline__ void ldsm_x4_t(uint32_t r[4], uint32_t saddr) {
    asm volatile("ldmatrix.sync.aligned.m8n8.x4.trans.shared.b16 {%0,%1,%2,%3}, [%4];"
                 : "=r"(r[0]), "=r"(r[1]), "=r"(r[2]), "=r"(r[3]) : "r"(saddr));
}

__device__ __forceinline__ uint32_t pack_bf2(float lo, float hi) {
    __nv_bfloat162 p = __floats2bfloat162_rn(lo, hi);   // .x = lo (low halfword)
    return *(uint32_t*)&p;
}

__device__ __forceinline__ void cp_async16(uint32_t smem_dst, const void* gsrc) {
    asm volatile("cp.async.cg.shared.global [%0], [%1], 16;\n"
                 :: "r"(smem_dst), "l"(gsrc));
}
__device__ __forceinline__ void cp_commit() {
    asm volatile("cp.async.commit_group;\n");
}
__device__ __forceinline__ void cp_wait0() {
    asm volatile("cp.async.wait_group 0;\n");
}

// ---------------- fp32 -> bf16 conversion kernels ----------------
__global__ __launch_bounds__(256)
void cvt_hid_kernel(const float* __restrict__ src, __nv_bfloat16* __restrict__ dst) {
    const long i = ((long)blockIdx.x * 256 + threadIdx.x) * 4;
    float4 v = *(const float4*)(src + i);
    *(uint2*)(dst + i) = make_uint2(pack_bf2(v.x, v.y), pack_bf2(v.z, v.w));
}
__global__ __launch_bounds__(256)
void cvt_w_kernel(const float* __restrict__ W0, const float* __restrict__ W1,
                  const float* __restrict__ W2, const float* __restrict__ W3,
                  __nv_bfloat16* __restrict__ dst) {
    const int z = blockIdx.z;
    const float* src = (z == 0) ? W0 : (z == 1) ? W1 : (z == 2) ? W2 : W3;
    const long i = ((long)blockIdx.x * 256 + threadIdx.x) * 4;
    float4 v = *(const float4*)(src + i);
    *(uint2*)(dst + (long)z * WSZ + i) =
        make_uint2(pack_bf2(v.x, v.y), pack_bf2(v.z, v.w));
}

// ---------------- BF16 GEMM, 2-stage cp.async (wait_group 0 only) -----------
// C[M,768] = A[M,768] @ W[N,768]^T + bias. A,W bf16 in gmem (pre-converted).
// BM=BN=128, BK=32 halves, 256 thr, 8 warps (warp tile 32x64), 2-buffer smem.
// Exactly one cp.async group in flight; wait_group 0 + barrier each step.
#define GK 768
#define BKH 32             // k per buffer (halves)
#define BSW 20             // smem row stride in 32-bit words
#define ROWB2 80           // smem row stride bytes
#define BUFB2 (128*ROWB2)  // 10240 B per operand per buffer

template<bool CBF>
__global__ __launch_bounds__(256, 2)
void bf16_gemm_ca2(const __nv_bfloat16* __restrict__ A,
                   const __nv_bfloat16* __restrict__ Wbase, long wstride,
                   const float* __restrict__ b0, const float* __restrict__ b1,
                   const float* __restrict__ b2,
                   void* __restrict__ C0, void* __restrict__ C1,
                   void* __restrict__ C2, int N)
{
    extern __shared__ uint32_t sm[];
    // layout: Abuf0 | Abuf1 | Bbuf0 | Bbuf1, each BUFB2 bytes
    const int z = blockIdx.z;
    const float* bias = (z == 0) ? b0 : (z == 1) ? b1 : b2;
    void* Cout        = (z == 0) ? C0 : (z == 1) ? C1 : C2;
    const __nv_bfloat16* W = Wbase + (long)z * wstride;

    const int t     = threadIdx.x;
    const int warp  = t >> 5;
    const int lane  = t & 31;
    const int warpM = warp >> 1;
    const int warpN = warp & 1;
    const int cRow  = blockIdx.y * 128;
    const int cCol  = blockIdx.x * 128;

    const int aRow  = t >> 2;           // 0..63 (2 passes of 64 rows)
    const int aColB = (t & 3) * 16;     // byte col within 32-half row

    const char* Ag = (const char*)(A + (long)(cRow + aRow) * GK) + aColB;
    const char* Wg = (const char*)(W + (long)(cCol + aRow) * GK) + aColB;
    const long ROWSTEP = (long)64 * GK * 2;

    const uint32_t sb = (uint32_t)__cvta_generic_to_shared(sm);
    const uint32_t sA = sb + (uint32_t)(aRow * ROWB2 + aColB);
    const uint32_t sBb = sA + 2 * BUFB2;

    // prologue: buffer 0
    {
        cp_async16(sA,                Ag);
        cp_async16(sA + 64 * ROWB2,   Ag + ROWSTEP);
        cp_async16(sBb,               Wg);
        cp_async16(sBb + 64 * ROWB2,  Wg + ROWSTEP);
        cp_commit();
        cp_wait0();
    }
    __syncthreads();

    float acc[2][8][4];
    #pragma unroll
    for (int i = 0; i < 2; i++)
        #pragma unroll
        for (int j = 0; j < 8; j++)
            #pragma unroll
            for (int r = 0; r < 4; r++) acc[i][j][r] = 0.f;

    const int lq = lane >> 2;
    const int lr = lane & 3;

    const uint32_t aoff = (uint32_t)((lane & 15) * ROWB2 + ((lane >> 4) << 4));
    const uint32_t boff = (uint32_t)(((lane & 7) + ((lane >> 4) << 3)) * ROWB2
                                     + (((lane >> 3) & 1) << 4));
    const uint32_t aA0 = sb + (uint32_t)(warpM * 32 * ROWB2) + aoff;
    const uint32_t bB0 = sb + 2 * BUFB2 + (uint32_t)(warpN * 64 * ROWB2) + boff;

    int buf = 0;
    for (int kt = 0; kt < GK; kt += BKH) {
        const bool more = (kt + BKH) < GK;
        if (more) {
            const long gk = (long)(kt + BKH) * 2;
            const uint32_t so = (uint32_t)((buf ^ 1) * BUFB2);
            cp_async16(sA + so,               Ag + gk);
            cp_async16(sA + so + 64 * ROWB2,  Ag + gk + ROWSTEP);
            cp_async16(sBb + so,              Wg + gk);
            cp_async16(sBb + so + 64 * ROWB2, Wg + gk + ROWSTEP);
            cp_commit();
        }

        const uint32_t ab  = aA0 + buf * BUFB2;
        const uint32_t bb0 = bB0 + buf * BUFB2;

        #pragma unroll
        for (int kb = 0; kb < 2; kb++) {
            uint32_t a0[4], a1[4];
            ldsm_x4(a0, ab + kb * 32);
            ldsm_x4(a1, ab + 16 * ROWB2 + kb * 32);
            #pragma unroll
            for (int nt2 = 0; nt2 < 4; nt2++) {
                uint32_t bbr[4];
                ldsm_x4(bbr, bb0 + nt2 * (16 * ROWB2) + kb * 32);
                mma_bf16(acc[0][nt2 * 2],     a0, bbr[0], bbr[1]);
                mma_bf16(acc[0][nt2 * 2 + 1], a0, bbr[2], bbr[3]);
                mma_bf16(acc[1][nt2 * 2],     a1, bbr[0], bbr[1]);
                mma_bf16(acc[1][nt2 * 2 + 1], a1, bbr[2], bbr[3]);
            }
        }

        if (more) cp_wait0();
        __syncthreads();
        buf ^= 1;
    }

    // ---- epilogue ----
    #pragma unroll
    for (int nt = 0; nt < 8; nt++) {
        const int col = cCol + warpN * 64 + nt * 8 + lr * 2;
        const float2 bb = *(const float2*)(bias + col);
        #pragma unroll
        for (int mt = 0; mt < 2; mt++) {
            const int row = cRow + warpM * 32 + mt * 16 + lq;
            float c0 = acc[mt][nt][0] + bb.x;
            float c1 = acc[mt][nt][1] + bb.y;
            float c2 = acc[mt][nt][2] + bb.x;
            float c3 = acc[mt][nt][3] + bb.y;
            if (CBF) {
                __nv_bfloat16* Cb = (__nv_bfloat16*)Cout;
                *(uint32_t*)(Cb + (long)row * N + col)       = pack_bf2(c0, c1);
                *(uint32_t*)(Cb + (long)(row + 8) * N + col) = pack_bf2(c2, c3);
            } else {
                float* Cf = (float*)Cout;
                *(float2*)(Cf + (long)row * N + col)       = make_float2(c0, c1);
                *(float2*)(Cf + (long)(row + 8) * N + col) = make_float2(c2, c3);
            }
        }
    }
}

// ---------------- BF16 flash attention: 4 warps x 32 q-rows, cp.async K/V ---
// smem rows (stride 144B): Q 0-127 | K0 128-191 | V0 192-255 | K1 256-319 |
// V1 320-383 | P 384-511 | mask. Double-buffered K/V, one group in flight.
#define FW 36     // row stride in 32-bit words (72 bf16)
#define ROWB 144  // row stride bytes

__global__ __launch_bounds__(128, 2)
void flash_bf16_kernel(const __nv_bfloat16* __restrict__ Q,
                       const __nv_bfloat16* __restrict__ Kx,
                       const __nv_bfloat16* __restrict__ Vx,
                       const float* __restrict__ mask,
                       const float* __restrict__ head_mask,
                       __nv_bfloat16* __restrict__ Cx)
{
    extern __shared__ uint32_t fsm[];
    float* Ms = (float*)(fsm + 512 * FW);    // [1024] mask row

    const int bh = blockIdx.y;
    const int b  = bh / NH;
    const int h  = bh % NH;
    const int q0 = blockIdx.x * 128;
    const int t  = threadIdx.x;
    const int warp = t >> 5, lane = t & 31;
    const int lq = lane >> 2, lr = lane & 3;
    const int qrow = warp * 32;

    const __nv_bfloat16* Qg = Q  + (long)b * NS * ND + (long)h * NHD;
    const __nv_bfloat16* Kg = Kx + (long)b * NS * ND + (long)h * NHD;
    const __nv_bfloat16* Vg = Vx + (long)b * NS * ND + (long)h * NHD;

    const uint32_t sb = (uint32_t)__cvta_generic_to_shared(fsm);
    const int seg = t & 7;           // 16B segment within a 128B row
    const int rb  = t >> 3;          // 0..15

    // Load Q tile [128 x 128B] via plain stores + mask; prefetch K/V tile 0
    {
        #pragma unroll
        for (int i = 0; i < 8; i++) {
            const int r = i * 16 + rb;
            uint4 qv = *(const uint4*)((const char*)(Qg + (long)(q0 + r) * ND) + seg * 16);
            *(uint4*)((char*)fsm + r * ROWB + seg * 16) = qv;
        }
        *(float4*)&Ms[t * 8]     = *(const float4*)(mask + b * NS + t * 8);
        *(float4*)&Ms[t * 8 + 4] = *(const float4*)(mask + b * NS + t * 8 + 4);

        // K/V tile 0 -> buffer 0
        #pragma unroll
        for (int i = 0; i < 4; i++) {
            const int r = i * 16 + rb;
            cp_async16(sb + (uint32_t)((128 + r) * ROWB + seg * 16),
                       (const char*)(Kg + (long)r * ND) + seg * 16);
            cp_async16(sb + (uint32_t)((192 + r) * ROWB + seg * 16),
                       (const char*)(Vg + (long)r * ND) + seg * 16);
        }
        cp_commit();
        cp_wait0();
    }
    __syncthreads();

    // ldmatrix per-lane byte offsets
    const uint32_t aoff = (uint32_t)((lane & 15) * ROWB + ((lane >> 4) << 4));
    const uint32_t koff = (uint32_t)(((lane & 7) + ((lane >> 4) << 3)) * ROWB
                                     + (((lane >> 3) & 1) << 4));
    const uint32_t voff = (uint32_t)(((lane & 7) + (((lane >> 3) & 1) << 3)) * ROWB
                                     + ((lane >> 4) << 4));

    const uint32_t qA = sb + (uint32_t)(qrow * ROWB) + aoff;
    const uint32_t pA = sb + (uint32_t)((384 + qrow) * ROWB) + aoff;

    // Cache Q fragments (loop-invariant)
    uint32_t qf[2][4][4];
    #pragma unroll
    for (int mt = 0; mt < 2; mt++)
        #pragma unroll
        for (int ks = 0; ks < 4; ks++)
            ldsm_x4(qf[mt][ks], qA + mt * (16 * ROWB) + ks * 32);

    float acc_o[2][8][4];
    #pragma unroll
    for (int mt = 0; mt < 2; mt++)
        #pragma unroll
        for (int nt = 0; nt < 8; nt++)
            #pragma unroll
            for (int j = 0; j < 4; j++) acc_o[mt][nt][j] = 0.f;
    float m[4], l[4];
    #pragma unroll
    for (int i = 0; i < 4; i++) { m[i] = -3.4e38f; l[i] = 0.f; }

    int buf = 0;
    for (int it = 0; it < 16; it++) {
        const int k0 = it * 64;
        const bool more = it < 15;

        // prefetch next K/V tile into the other buffer
        if (more) {
            const int nbase = 128 + (buf ^ 1) * 128;
            #pragma unroll
            for (int i = 0; i < 4; i++) {
                const int r = i * 16 + rb;
                cp_async16(sb + (uint32_t)((nbase + r) * ROWB + seg * 16),
                           (const char*)(Kg + (long)(k0 + 64 + r) * ND) + seg * 16);
                cp_async16(sb + (uint32_t)((nbase + 64 + r) * ROWB + seg * 16),
                           (const char*)(Vg + (long)(k0 + 64 + r) * ND) + seg * 16);
            }
            cp_commit();
        }

        const uint32_t kB = sb + (uint32_t)((128 + buf * 128) * ROWB) + koff;
        const uint32_t vB = sb + (uint32_t)((192 + buf * 128) * ROWB) + voff;

        // ---- S = Q @ K^T (32 x 64 per warp) ----
        float acc_s[2][8][4];
        #pragma unroll
        for (int mt = 0; mt < 2; mt++)
            #pragma unroll
            for (int nt = 0; nt < 8; nt++)
                #pragma unroll
                for (int j = 0; j < 4; j++) acc_s[mt][nt][j] = 0.f;

        #pragma unroll
        for (int ks = 0; ks < 4; ks++) {
            #pragma unroll
            for (int nt2 = 0; nt2 < 4; nt2++) {
                uint32_t bb[4];
                ldsm_x4(bb, kB + nt2 * (16 * ROWB) + ks * 32);
                mma_bf16(acc_s[0][nt2 * 2],     qf[0][ks], bb[0], bb[1]);
                mma_bf16(acc_s[0][nt2 * 2 + 1], qf[0][ks], bb[2], bb[3]);
                mma_bf16(acc_s[1][nt2 * 2],     qf[1][ks], bb[0], bb[1]);
                mma_bf16(acc_s[1][nt2 * 2 + 1], qf[1][ks], bb[2], bb[3]);
            }
        }

        // ---- scale + mask + online softmax (per m-tile) ----
        #pragma unroll
        for (int mt = 0; mt < 2; mt++) {
            float mx0 = -3.4e38f, mx1 = -3.4e38f;
            #pragma unroll
            for (int nt = 0; nt < 8; nt++) {
                float2 mk = *(const float2*)&Ms[k0 + nt * 8 + lr * 2];
                acc_s[mt][nt][0] = fmaf(acc_s[mt][nt][0], 0.125f, mk.x);
                acc_s[mt][nt][1] = fmaf(acc_s[mt][nt][1], 0.125f, mk.y);
                acc_s[mt][nt][2] = fmaf(acc_s[mt][nt][2], 0.125f, mk.x);
                acc_s[mt][nt][3] = fmaf(acc_s[mt][nt][3], 0.125f, mk.y);
                mx0 = fmaxf(mx0, fmaxf(acc_s[mt][nt][0], acc_s[mt][nt][1]));
                mx1 = fmaxf(mx1, fmaxf(acc_s[mt][nt][2], acc_s[mt][nt][3]));
            }
            mx0 = fmaxf(mx0, __shfl_xor_sync(0xffffffffu, mx0, 1));
            mx0 = fmaxf(mx0, __shfl_xor_sync(0xffffffffu, mx0, 2));
            mx1 = fmaxf(mx1, __shfl_xor_sync(0xffffffffu, mx1, 1));
            mx1 = fmaxf(mx1, __shfl_xor_sync(0xffffffffu, mx1, 2));

            const float mn0 = fmaxf(m[mt * 2 + 0], mx0);
            const float mn1 = fmaxf(m[mt * 2 + 1], mx1);
            const float corr0 = __expf(m[mt * 2 + 0] - mn0);
            const float corr1 = __expf(m[mt * 2 + 1] - mn1);
            m[mt * 2 + 0] = mn0;
            m[mt * 2 + 1] = mn1;

            float ls0 = 0.f, ls1 = 0.f;
            #pragma unroll
            for (int nt = 0; nt < 8; nt++) {
                __nv_bfloat162 pb0 = __floats2bfloat162_rn(__expf(acc_s[mt][nt][0] - mn0),
                                                           __expf(acc_s[mt][nt][1] - mn0));
                __nv_bfloat162 pb1 = __floats2bfloat162_rn(__expf(acc_s[mt][nt][2] - mn1),
                                                           __expf(acc_s[mt][nt][3] - mn1));
                ls0 += __bfloat162float(pb0.x) + __bfloat162float(pb0.y);
                ls1 += __bfloat162float(pb1.x) + __bfloat162float(pb1.y);
                fsm[(384 + qrow + mt * 16 + lq) * FW + nt * 4 + lr]     = *(uint32_t*)&pb0;
                fsm[(384 + qrow + mt * 16 + lq + 8) * FW + nt * 4 + lr] = *(uint32_t*)&pb1;
            }
            ls0 += __shfl_xor_sync(0xffffffffu, ls0, 1);
            ls0 += __shfl_xor_sync(0xffffffffu, ls0, 2);
            ls1 += __shfl_xor_sync(0xffffffffu, ls1, 1);
            ls1 += __shfl_xor_sync(0xffffffffu, ls1, 2);
            l[mt * 2 + 0] = l[mt * 2 + 0] * corr0 + ls0;
            l[mt * 2 + 1] = l[mt * 2 + 1] * corr1 + ls1;

            #pragma unroll
            for (int nt = 0; nt < 8; nt++) {
                acc_o[mt][nt][0] *= corr0;
                acc_o[mt][nt][1] *= corr0;
                acc_o[mt][nt][2] *= corr1;
                acc_o[mt][nt][3] *= corr1;
            }
        }
        __syncwarp();   // Ps STS -> LDSM (cross-lane within warp)

        // ---- O += P @ V, k-dim = key (4 blocks of 16) ----
        #pragma unroll
        for (int kb = 0; kb < 4; kb++) {
            uint32_t pa0[4], pa1[4];
            ldsm_x4(pa0, pA + kb * 32);
            ldsm_x4(pa1, pA + 16 * ROWB + kb * 32);
            #pragma unroll
            for (int nd2 = 0; nd2 < 4; nd2++) {
                uint32_t bb[4];
                ldsm_x4_t(bb, vB + kb * (16 * ROWB) + nd2 * 32);
                mma_bf16(acc_o[0][nd2 * 2],     pa0, bb[0], bb[1]);
                mma_bf16(acc_o[0][nd2 * 2 + 1], pa0, bb[2], bb[3]);
                mma_bf16(acc_o[1][nd2 * 2],     pa1, bb[0], bb[1]);
                mma_bf16(acc_o[1][nd2 * 2 + 1], pa1, bb[2], bb[3]);
            }
        }

        if (more) cp_wait0();   // next tile's K/V landed
        __syncthreads();        // all warps done with current buffer
        buf ^= 1;
    }

    // ---- epilogue: normalize, head_mask, write ctx (bf16) ----
    const float hm = head_mask[h];
    #pragma unroll
    for (int mt = 0; mt < 2; mt++) {
        const float inv0 = hm / l[mt * 2 + 0];
        const float inv1 = hm / l[mt * 2 + 1];
        #pragma unroll
        for (int nt = 0; nt < 8; nt++) {
            const int col = h * NHD + nt * 8 + lr * 2;
            const long r0 = (long)b * NS + q0 + qrow + mt * 16 + lq;
            *(uint32_t*)(Cx + r0 * ND + col) =
                pack_bf2(acc_o[mt][nt][0] * inv0, acc_o[mt][nt][1] * inv0);
            *(uint32_t*)(Cx + (r0 + 8) * ND + col) =
                pack_bf2(acc_o[mt][nt][2] * inv1, acc_o[mt][nt][3] * inv1);
        }
    }
}

// ---------------- residual + LayerNorm ----------------
__global__ __launch_bounds__(256)
void ln_kernel(const float* __restrict__ proj, const float* __restrict__ hidden,
               const float* __restrict__ gamma, const float* __restrict__ beta,
               float* __restrict__ out)
{
    const long row = blockIdx.x;
    const int t = threadIdx.x;
    float x[3];
    #pragma unroll
    for (int k = 0; k < 3; k++) {
        long idx = row * ND + t + k * 256;
        x[k] = proj[idx] + hidden[idx];
    }
    float s = x[0] + x[1] + x[2];
    float mu = blockSum(s) * (1.0f / ND);
    float vs = 0.f;
    #pragma unroll
    for (int k = 0; k < 3; k++) { float d = x[k] - mu; vs += d * d; }
    float var = blockSum(vs) * (1.0f / ND);
    float rstd = rsqrtf(var + 1e-12f);
    #pragma unroll
    for (int k = 0; k < 3; k++) {
        int c = t + k * 256;
        out[row * ND + c] = (x[k] - mu) * rstd * gamma[c] + beta[c];
    }
}

// ---------------- launch ----------------
extern "C" void kernel_launch(void* const* d_in, const int* in_sizes, int n_in,
                              void* d_out, int out_size)
{
    const float* hidden    = (const float*)d_in[0];
    const float* attn_mask = (const float*)d_in[1];
    const float* head_mask = (const float*)d_in[2];
    const float* Wq = (const float*)d_in[3];
    const float* bq = (const float*)d_in[4];
    const float* Wk = (const float*)d_in[5];
    const float* bk = (const float*)d_in[6];
    const float* Wv = (const float*)d_in[7];
    const float* bv = (const float*)d_in[8];
    const float* Wo = (const float*)d_in[9];
    const float* bo = (const float*)d_in[10];
    const float* gamma = (const float*)d_in[11];
    const float* beta  = (const float*)d_in[12];
    float* out = (float*)d_out;

    void *pq, *pk, *pv, *pc, *pp, *ph, *pw;
    cudaGetSymbolAddress(&pq, g_q);
    cudaGetSymbolAddress(&pk, g_k);
    cudaGetSymbolAddress(&pv, g_v);
    cudaGetSymbolAddress(&pc, g_ctx);
    cudaGetSymbolAddress(&pp, g_proj);
    cudaGetSymbolAddress(&ph, g_hid);
    cudaGetSymbolAddress(&pw, g_wb);
    __nv_bfloat16* q   = (__nv_bfloat16*)pq;
    __nv_bfloat16* k   = (__nv_bfloat16*)pk;
    __nv_bfloat16* v   = (__nv_bfloat16*)pv;
    __nv_bfloat16* cx  = (__nv_bfloat16*)pc;
    float*         pr  = (float*)pp;
    __nv_bfloat16* hb  = (__nv_bfloat16*)ph;
    __nv_bfloat16* wb  = (__nv_bfloat16*)pw;

    const int FLASH_SMEM = 512 * FW * 4 + 4096;   // 77824 B
    const int GEMM_SMEM  = 4 * 128 * BSW * 4;     // 40960 B
    static int attr_set = 0;
    if (!attr_set) {
        cudaFuncSetAttribute(flash_bf16_kernel,
                             cudaFuncAttributeMaxDynamicSharedMemorySize, FLASH_SMEM);
        cudaFuncSetAttribute(bf16_gemm_ca2<true>,
                             cudaFuncAttributeMaxDynamicSharedMemorySize, GEMM_SMEM);
        cudaFuncSetAttribute(bf16_gemm_ca2<false>,
                             cudaFuncAttributeMaxDynamicSharedMemorySize, GEMM_SMEM);
        attr_set = 1;
    }

    // pre-convert hidden + weights to bf16
    cvt_hid_kernel<<<NM * ND / 4 / 256, 256>>>(hidden, hb);
    dim3 gW(WSZ / 4 / 256, 1, 4);   // (576,1,4)
    cvt_w_kernel<<<gW, 256>>>(Wq, Wk, Wv, Wo, wb);

    // fused QKV: gridDim.z = 3 selects (Wq,bq,q), (Wk,bk,k), (Wv,bv,v)
    dim3 gQKV(ND / 128, NM / 128, 3);   // (6, 64, 3)
    bf16_gemm_ca2<true><<<gQKV, 256, GEMM_SMEM>>>(
        hb, wb, (long)WSZ, bq, bk, bv, q, k, v, ND);

    dim3 gF(NS / 128, NBH);             // (8, 96)
    flash_bf16_kernel<<<gF, 128, FLASH_SMEM>>>(q, k, v, attn_mask, head_mask, cx);

    dim3 gO(ND / 128, NM / 128, 1);     // (6, 64, 1)
    bf16_gemm_ca2<false><<<gO, 256, GEMM_SMEM>>>(
        cx, wb + 3 * WSZ, 0L, bo, bo, bo, pr, pr, pr, ND);

    ln_kernel<<<NM, 256>>>(pr, hidden, gamma, beta, out);
}

// round 13
// speedup vs baseline: 1.9624x; 1.0623x over previous
#include <cuda_runtime.h>
#include <cuda_bf16.h>
#include <math.h>
#include <stdint.h>

// Problem constants
#define NB 8
#define NS 1024
#define ND 768
#define NH 12
#define NHD 64
#define NM (NB*NS)        // 8192 rows
#define NBH (NB*NH)       // 96 batch-head pairs
#define WSZ (ND*ND)       // 589824

#define LOG2E 1.4426950408889634f
#define QSCALE (0.125f * LOG2E)

// ---------------- scratch (static device globals; no allocation) ----------------
__device__ __nv_bfloat16 g_q  [NM*ND];
__device__ __nv_bfloat16 g_k  [NM*ND];
__device__ __nv_bfloat16 g_v  [NM*ND];
__device__ __nv_bfloat16 g_ctx[NM*ND];
__device__ float         g_proj[NM*ND];
__device__ __nv_bfloat16 g_hid[NM*ND];     // hidden pre-converted to bf16
__device__ __nv_bfloat16 g_wb [4*WSZ];     // Wq|Wk|Wv|Wo pre-converted to bf16

// ---------------- helpers ----------------
__device__ __forceinline__ float warpSum(float v) {
    #pragma unroll
    for (int o = 16; o; o >>= 1) v += __shfl_xor_sync(0xffffffffu, v, o);
    return v;
}
__device__ __forceinline__ float blockSum(float v) {
    __shared__ float s[8];
    __syncthreads();
    v = warpSum(v);
    if ((threadIdx.x & 31) == 0) s[threadIdx.x >> 5] = v;
    __syncthreads();
    if (threadIdx.x == 0) {
        float t = 0.f;
        #pragma unroll
        for (int i = 0; i < 8; i++) t += s[i];
        s[0] = t;
    }
    __syncthreads();
    return s[0];
}

__device__ __forceinline__ void mma_bf16(float d[4], const uint32_t a[4],
                                         const uint32_t b0, const uint32_t b1) {
    asm volatile(
        "mma.sync.aligned.m16n8k16.row.col.f32.bf16.bf16.f32 "
        "{%0,%1,%2,%3}, {%4,%5,%6,%7}, {%8,%9}, {%0,%1,%2,%3};\n"
        : "+f"(d[0]), "+f"(d[1]), "+f"(d[2]), "+f"(d[3])
        : "r"(a[0]), "r"(a[1]), "r"(a[2]), "r"(a[3]),
          "r"(b0), "r"(b1));
}

__device__ __forceinline__ void ldsm_x4(uint32_t r[4], uint32_t saddr) {
    asm volatile("ldmatrix.sync.aligned.m8n8.x4.shared.b16 {%0,%1,%2,%3}, [%4];"
                 : "=r"(r[0]), "=r"(r[1]), "=r"(r[2]), "=r"(r[3]) : "r"(saddr));
}
__device__ __forceinline__ void ldsm_x4_t(uint32_t r[4], uint32_t saddr) {
    asm volatile("ldmatrix.sync.aligned.m8n8.x4.trans.shared.b16 {%0,%1,%2,%3}, [%4];"
                 : "=r"(r[0]), "=r"(r[1]), "=r"(r[2]), "=r"(r[3]) : "r"(saddr));
}

__device__ __forceinline__ uint32_t pack_bf2(float lo, float hi) {
    __nv_bfloat162 p = __floats2bfloat162_rn(lo, hi);   // .x = lo (low halfword)
    return *(uint32_t*)&p;
}

__device__ __forceinline__ float ex2f(float x) {
    float r;
    asm("ex2.approx.ftz.f32 %0, %1;" : "=f"(r) : "f"(x));
    return r;
}

__device__ __forceinline__ void cp_async16(uint32_t smem_dst, const void* gsrc) {
    asm volatile("cp.async.cg.shared.global [%0], [%1], 16;\n"
                 :: "r"(smem_dst), "l"(gsrc));
}
__device__ __forceinline__ void cp_commit() {
    asm volatile("cp.async.commit_group;\n");
}
__device__ __forceinline__ void cp_wait0() {
    asm volatile("cp.async.wait_group 0;\n");
}

// ---------------- fp32 -> bf16 conversion kernels ----------------
__global__ __launch_bounds__(256)
void cvt_hid_kernel(const float* __restrict__ src, __nv_bfloat16* __restrict__ dst) {
    const long i = ((long)blockIdx.x * 256 + threadIdx.x) * 4;
    float4 v = *(const float4*)(src + i);
    *(uint2*)(dst + i) = make_uint2(pack_bf2(v.x, v.y), pack_bf2(v.z, v.w));
}
__global__ __launch_bounds__(256)
void cvt_w_kernel(const float* __restrict__ W0, const float* __restrict__ W1,
                  const float* __restrict__ W2, const float* __restrict__ W3,
                  __nv_bfloat16* __restrict__ dst) {
    const int z = blockIdx.z;
    const float* src = (z == 0) ? W0 : (z == 1) ? W1 : (z == 2) ? W2 : W3;
    const long i = ((long)blockIdx.x * 256 + threadIdx.x) * 4;
    float4 v = *(const float4*)(src + i);
    *(uint2*)(dst + (long)z * WSZ + i) =
        make_uint2(pack_bf2(v.x, v.y), pack_bf2(v.z, v.w));
}

// ---------------- BF16 GEMM, 2-stage cp.async (round 12, + epilogue scale) --
#define GK 768
#define BKH 32             // k per buffer (halves)
#define BSW 20             // smem row stride in 32-bit words
#define ROWB2 80           // smem row stride bytes
#define BUFB2 (128*ROWB2)  // 10240 B per operand per buffer

template<bool CBF>
__global__ __launch_bounds__(256, 2)
void bf16_gemm_ca2(const __nv_bfloat16* __restrict__ A,
                   const __nv_bfloat16* __restrict__ Wbase, long wstride,
                   const float* __restrict__ b0, const float* __restrict__ b1,
                   const float* __restrict__ b2,
                   void* __restrict__ C0, void* __restrict__ C1,
                   void* __restrict__ C2, int N,
                   float s0, float s1, float s2)
{
    extern __shared__ uint32_t sm[];
    const int z = blockIdx.z;
    const float* bias = (z == 0) ? b0 : (z == 1) ? b1 : b2;
    void* Cout        = (z == 0) ? C0 : (z == 1) ? C1 : C2;
    const float cscale = (z == 0) ? s0 : (z == 1) ? s1 : s2;
    const __nv_bfloat16* W = Wbase + (long)z * wstride;

    const int t     = threadIdx.x;
    const int warp  = t >> 5;
    const int lane  = t & 31;
    const int warpM = warp >> 1;
    const int warpN = warp & 1;
    const int cRow  = blockIdx.y * 128;
    const int cCol  = blockIdx.x * 128;

    const int aRow  = t >> 2;
    const int aColB = (t & 3) * 16;

    const char* Ag = (const char*)(A + (long)(cRow + aRow) * GK) + aColB;
    const char* Wg = (const char*)(W + (long)(cCol + aRow) * GK) + aColB;
    const long ROWSTEP = (long)64 * GK * 2;

    const uint32_t sb = (uint32_t)__cvta_generic_to_shared(sm);
    const uint32_t sA = sb + (uint32_t)(aRow * ROWB2 + aColB);
    const uint32_t sBb = sA + 2 * BUFB2;

    {
        cp_async16(sA,                Ag);
        cp_async16(sA + 64 * ROWB2,   Ag + ROWSTEP);
        cp_async16(sBb,               Wg);
        cp_async16(sBb + 64 * ROWB2,  Wg + ROWSTEP);
        cp_commit();
        cp_wait0();
    }
    __syncthreads();

    float acc[2][8][4];
    #pragma unroll
    for (int i = 0; i < 2; i++)
        #pragma unroll
        for (int j = 0; j < 8; j++)
            #pragma unroll
            for (int r = 0; r < 4; r++) acc[i][j][r] = 0.f;

    const int lq = lane >> 2;
    const int lr = lane & 3;

    const uint32_t aoff = (uint32_t)((lane & 15) * ROWB2 + ((lane >> 4) << 4));
    const uint32_t boff = (uint32_t)(((lane & 7) + ((lane >> 4) << 3)) * ROWB2
                                     + (((lane >> 3) & 1) << 4));
    const uint32_t aA0 = sb + (uint32_t)(warpM * 32 * ROWB2) + aoff;
    const uint32_t bB0 = sb + 2 * BUFB2 + (uint32_t)(warpN * 64 * ROWB2) + boff;

    int buf = 0;
    for (int kt = 0; kt < GK; kt += BKH) {
        const bool more = (kt + BKH) < GK;
        if (more) {
            const long gk = (long)(kt + BKH) * 2;
            const uint32_t so = (uint32_t)((buf ^ 1) * BUFB2);
            cp_async16(sA + so,               Ag + gk);
            cp_async16(sA + so + 64 * ROWB2,  Ag + gk + ROWSTEP);
            cp_async16(sBb + so,              Wg + gk);
            cp_async16(sBb + so + 64 * ROWB2, Wg + gk + ROWSTEP);
            cp_commit();
        }

        const uint32_t ab  = aA0 + buf * BUFB2;
        const uint32_t bb0 = bB0 + buf * BUFB2;

        #pragma unroll
        for (int kb = 0; kb < 2; kb++) {
            uint32_t a0[4], a1[4];
            ldsm_x4(a0, ab + kb * 32);
            ldsm_x4(a1, ab + 16 * ROWB2 + kb * 32);
            #pragma unroll
            for (int nt2 = 0; nt2 < 4; nt2++) {
                uint32_t bbr[4];
                ldsm_x4(bbr, bb0 + nt2 * (16 * ROWB2) + kb * 32);
                mma_bf16(acc[0][nt2 * 2],     a0, bbr[0], bbr[1]);
                mma_bf16(acc[0][nt2 * 2 + 1], a0, bbr[2], bbr[3]);
                mma_bf16(acc[1][nt2 * 2],     a1, bbr[0], bbr[1]);
                mma_bf16(acc[1][nt2 * 2 + 1], a1, bbr[2], bbr[3]);
            }
        }

        if (more) cp_wait0();
        __syncthreads();
        buf ^= 1;
    }

    // ---- epilogue: (acc + bias) * cscale ----
    #pragma unroll
    for (int nt = 0; nt < 8; nt++) {
        const int col = cCol + warpN * 64 + nt * 8 + lr * 2;
        const float2 bb = *(const float2*)(bias + col);
        #pragma unroll
        for (int mt = 0; mt < 2; mt++) {
            const int row = cRow + warpM * 32 + mt * 16 + lq;
            float c0 = (acc[mt][nt][0] + bb.x) * cscale;
            float c1 = (acc[mt][nt][1] + bb.y) * cscale;
            float c2 = (acc[mt][nt][2] + bb.x) * cscale;
            float c3 = (acc[mt][nt][3] + bb.y) * cscale;
            if (CBF) {
                __nv_bfloat16* Cb = (__nv_bfloat16*)Cout;
                *(uint32_t*)(Cb + (long)row * N + col)       = pack_bf2(c0, c1);
                *(uint32_t*)(Cb + (long)(row + 8) * N + col) = pack_bf2(c2, c3);
            } else {
                float* Cf = (float*)Cout;
                *(float2*)(Cf + (long)row * N + col)       = make_float2(c0, c1);
                *(float2*)(Cf + (long)(row + 8) * N + col) = make_float2(c2, c3);
            }
        }
    }
}

// ---------------- BF16 flash attention: P in registers (FA-2), exp2 domain --
// Q pre-scaled by 0.125*log2e in QKV epilogue; mask staged *log2e.
// smem rows (stride 144B): Q 0-127 | K0 128-191 | V0 192-255 | K1 256-319 |
// V1 320-383 | mask after. Double-buffered K/V via cp.async (1 group in flight).
#define FW 36     // row stride in 32-bit words (72 bf16)
#define ROWB 144  // row stride bytes

__global__ __launch_bounds__(128, 2)
void flash_bf16_kernel(const __nv_bfloat16* __restrict__ Q,
                       const __nv_bfloat16* __restrict__ Kx,
                       const __nv_bfloat16* __restrict__ Vx,
                       const float* __restrict__ mask,
                       const float* __restrict__ head_mask,
                       __nv_bfloat16* __restrict__ Cx)
{
    extern __shared__ uint32_t fsm[];
    float* Ms = (float*)(fsm + 384 * FW);    // [1024] mask row (already *log2e)

    const int bh = blockIdx.y;
    const int b  = bh / NH;
    const int h  = bh % NH;
    const int q0 = blockIdx.x * 128;
    const int t  = threadIdx.x;
    const int warp = t >> 5, lane = t & 31;
    const int lq = lane >> 2, lr = lane & 3;
    const int qrow = warp * 32;

    const __nv_bfloat16* Qg = Q  + (long)b * NS * ND + (long)h * NHD;
    const __nv_bfloat16* Kg = Kx + (long)b * NS * ND + (long)h * NHD;
    const __nv_bfloat16* Vg = Vx + (long)b * NS * ND + (long)h * NHD;

    const uint32_t sb = (uint32_t)__cvta_generic_to_shared(fsm);
    const int seg = t & 7;
    const int rb  = t >> 3;

    // Q tile + mask (*log2e); prefetch K/V tile 0
    {
        #pragma unroll
        for (int i = 0; i < 8; i++) {
            const int r = i * 16 + rb;
            uint4 qv = *(const uint4*)((const char*)(Qg + (long)(q0 + r) * ND) + seg * 16);
            *(uint4*)((char*)fsm + r * ROWB + seg * 16) = qv;
        }
        float4 m0v = *(const float4*)(mask + b * NS + t * 8);
        float4 m1v = *(const float4*)(mask + b * NS + t * 8 + 4);
        m0v.x *= LOG2E; m0v.y *= LOG2E; m0v.z *= LOG2E; m0v.w *= LOG2E;
        m1v.x *= LOG2E; m1v.y *= LOG2E; m1v.z *= LOG2E; m1v.w *= LOG2E;
        *(float4*)&Ms[t * 8]     = m0v;
        *(float4*)&Ms[t * 8 + 4] = m1v;

        #pragma unroll
        for (int i = 0; i < 4; i++) {
            const int r = i * 16 + rb;
            cp_async16(sb + (uint32_t)((128 + r) * ROWB + seg * 16),
                       (const char*)(Kg + (long)r * ND) + seg * 16);
            cp_async16(sb + (uint32_t)((192 + r) * ROWB + seg * 16),
                       (const char*)(Vg + (long)r * ND) + seg * 16);
        }
        cp_commit();
        cp_wait0();
    }
    __syncthreads();

    // ldmatrix per-lane byte offsets
    const uint32_t aoff = (uint32_t)((lane & 15) * ROWB + ((lane >> 4) << 4));
    const uint32_t koff = (uint32_t)(((lane & 7) + ((lane >> 4) << 3)) * ROWB
                                     + (((lane >> 3) & 1) << 4));
    const uint32_t voff = (uint32_t)(((lane & 7) + (((lane >> 3) & 1) << 3)) * ROWB
                                     + ((lane >> 4) << 4));

    const uint32_t qA = sb + (uint32_t)(qrow * ROWB) + aoff;

    // Cache Q fragments (loop-invariant)
    uint32_t qf[2][4][4];
    #pragma unroll
    for (int mt = 0; mt < 2; mt++)
        #pragma unroll
        for (int ks = 0; ks < 4; ks++)
            ldsm_x4(qf[mt][ks], qA + mt * (16 * ROWB) + ks * 32);

    float acc_o[2][8][4];
    #pragma unroll
    for (int mt = 0; mt < 2; mt++)
        #pragma unroll
        for (int nt = 0; nt < 8; nt++)
            #pragma unroll
            for (int j = 0; j < 4; j++) acc_o[mt][nt][j] = 0.f;
    float m[4], l[4];
    #pragma unroll
    for (int i = 0; i < 4; i++) { m[i] = -3.4e38f; l[i] = 0.f; }

    int buf = 0;
    for (int it = 0; it < 16; it++) {
        const int k0 = it * 64;
        const bool more = it < 15;

        if (more) {
            const int nbase = 128 + (buf ^ 1) * 128;
            #pragma unroll
            for (int i = 0; i < 4; i++) {
                const int r = i * 16 + rb;
                cp_async16(sb + (uint32_t)((nbase + r) * ROWB + seg * 16),
                           (const char*)(Kg + (long)(k0 + 64 + r) * ND) + seg * 16);
                cp_async16(sb + (uint32_t)((nbase + 64 + r) * ROWB + seg * 16),
                           (const char*)(Vg + (long)(k0 + 64 + r) * ND) + seg * 16);
            }
            cp_commit();
        }

        const uint32_t kB = sb + (uint32_t)((128 + buf * 128) * ROWB) + koff;
        const uint32_t vB = sb + (uint32_t)((192 + buf * 128) * ROWB) + voff;

        // ---- S = Q @ K^T (32 x 64 per warp); acc_s = log2e*(qk/8) ----
        float acc_s[2][8][4];
        #pragma unroll
        for (int mt = 0; mt < 2; mt++)
            #pragma unroll
            for (int nt = 0; nt < 8; nt++)
                #pragma unroll
                for (int j = 0; j < 4; j++) acc_s[mt][nt][j] = 0.f;

        #pragma unroll
        for (int ks = 0; ks < 4; ks++) {
            #pragma unroll
            for (int nt2 = 0; nt2 < 4; nt2++) {
                uint32_t bb[4];
                ldsm_x4(bb, kB + nt2 * (16 * ROWB) + ks * 32);
                mma_bf16(acc_s[0][nt2 * 2],     qf[0][ks], bb[0], bb[1]);
                mma_bf16(acc_s[0][nt2 * 2 + 1], qf[0][ks], bb[2], bb[3]);
                mma_bf16(acc_s[1][nt2 * 2],     qf[1][ks], bb[0], bb[1]);
                mma_bf16(acc_s[1][nt2 * 2 + 1], qf[1][ks], bb[2], bb[3]);
            }
        }

        // ---- mask add + online softmax (base-2); P packed to registers ----
        uint32_t pf[2][8][2];
        #pragma unroll
        for (int mt = 0; mt < 2; mt++) {
            float mx0 = -3.4e38f, mx1 = -3.4e38f;
            #pragma unroll
            for (int nt = 0; nt < 8; nt++) {
                float2 mk = *(const float2*)&Ms[k0 + nt * 8 + lr * 2];
                acc_s[mt][nt][0] += mk.x;
                acc_s[mt][nt][1] += mk.y;
                acc_s[mt][nt][2] += mk.x;
                acc_s[mt][nt][3] += mk.y;
                mx0 = fmaxf(mx0, fmaxf(acc_s[mt][nt][0], acc_s[mt][nt][1]));
                mx1 = fmaxf(mx1, fmaxf(acc_s[mt][nt][2], acc_s[mt][nt][3]));
            }
            mx0 = fmaxf(mx0, __shfl_xor_sync(0xffffffffu, mx0, 1));
            mx0 = fmaxf(mx0, __shfl_xor_sync(0xffffffffu, mx0, 2));
            mx1 = fmaxf(mx1, __shfl_xor_sync(0xffffffffu, mx1, 1));
            mx1 = fmaxf(mx1, __shfl_xor_sync(0xffffffffu, mx1, 2));

            const float mn0 = fmaxf(m[mt * 2 + 0], mx0);
            const float mn1 = fmaxf(m[mt * 2 + 1], mx1);
            const float corr0 = ex2f(m[mt * 2 + 0] - mn0);
            const float corr1 = ex2f(m[mt * 2 + 1] - mn1);
            m[mt * 2 + 0] = mn0;
            m[mt * 2 + 1] = mn1;

            float ls0 = 0.f, ls1 = 0.f;
            #pragma unroll
            for (int nt = 0; nt < 8; nt++) {
                __nv_bfloat162 pb0 = __floats2bfloat162_rn(ex2f(acc_s[mt][nt][0] - mn0),
                                                           ex2f(acc_s[mt][nt][1] - mn0));
                __nv_bfloat162 pb1 = __floats2bfloat162_rn(ex2f(acc_s[mt][nt][2] - mn1),
                                                           ex2f(acc_s[mt][nt][3] - mn1));
                ls0 += __bfloat162float(pb0.x) + __bfloat162float(pb0.y);
                ls1 += __bfloat162float(pb1.x) + __bfloat162float(pb1.y);
                pf[mt][nt][0] = *(uint32_t*)&pb0;
                pf[mt][nt][1] = *(uint32_t*)&pb1;
            }
            ls0 += __shfl_xor_sync(0xffffffffu, ls0, 1);
            ls0 += __shfl_xor_sync(0xffffffffu, ls0, 2);
            ls1 += __shfl_xor_sync(0xffffffffu, ls1, 1);
            ls1 += __shfl_xor_sync(0xffffffffu, ls1, 2);
            l[mt * 2 + 0] = l[mt * 2 + 0] * corr0 + ls0;
            l[mt * 2 + 1] = l[mt * 2 + 1] * corr1 + ls1;

            #pragma unroll
            for (int nt = 0; nt < 8; nt++) {
                acc_o[mt][nt][0] *= corr0;
                acc_o[mt][nt][1] *= corr0;
                acc_o[mt][nt][2] *= corr1;
                acc_o[mt][nt][3] *= corr1;
            }
        }

        // ---- O += P @ V : P A-fragments come straight from pf registers ----
        #pragma unroll
        for (int kb = 0; kb < 4; kb++) {
            uint32_t a0[4] = {pf[0][2*kb][0], pf[0][2*kb][1],
                              pf[0][2*kb+1][0], pf[0][2*kb+1][1]};
            uint32_t a1[4] = {pf[1][2*kb][0], pf[1][2*kb][1],
                              pf[1][2*kb+1][0], pf[1][2*kb+1][1]};
            #pragma unroll
            for (int nd2 = 0; nd2 < 4; nd2++) {
                uint32_t bb[4];
                ldsm_x4_t(bb, vB + kb * (16 * ROWB) + nd2 * 32);
                mma_bf16(acc_o[0][nd2 * 2],     a0, bb[0], bb[1]);
                mma_bf16(acc_o[0][nd2 * 2 + 1], a0, bb[2], bb[3]);
                mma_bf16(acc_o[1][nd2 * 2],     a1, bb[0], bb[1]);
                mma_bf16(acc_o[1][nd2 * 2 + 1], a1, bb[2], bb[3]);
            }
        }

        if (more) cp_wait0();
        __syncthreads();
        buf ^= 1;
    }

    // ---- epilogue: normalize, head_mask, write ctx (bf16) ----
    const float hm = head_mask[h];
    #pragma unroll
    for (int mt = 0; mt < 2; mt++) {
        const float inv0 = hm / l[mt * 2 + 0];
        const float inv1 = hm / l[mt * 2 + 1];
        #pragma unroll
        for (int nt = 0; nt < 8; nt++) {
            const int col = h * NHD + nt * 8 + lr * 2;
            const long r0 = (long)b * NS + q0 + qrow + mt * 16 + lq;
            *(uint32_t*)(Cx + r0 * ND + col) =
                pack_bf2(acc_o[mt][nt][0] * inv0, acc_o[mt][nt][1] * inv0);
            *(uint32_t*)(Cx + (r0 + 8) * ND + col) =
                pack_bf2(acc_o[mt][nt][2] * inv1, acc_o[mt][nt][3] * inv1);
        }
    }
}

// ---------------- residual + LayerNorm ----------------
__global__ __launch_bounds__(256)
void ln_kernel(const float* __restrict__ proj, const float* __restrict__ hidden,
               const float* __restrict__ gamma, const float* __restrict__ beta,
               float* __restrict__ out)
{
    const long row = blockIdx.x;
    const int t = threadIdx.x;
    float x[3];
    #pragma unroll
    for (int k = 0; k < 3; k++) {
        long idx = row * ND + t + k * 256;
        x[k] = proj[idx] + hidden[idx];
    }
    float s = x[0] + x[1] + x[2];
    float mu = blockSum(s) * (1.0f / ND);
    float vs = 0.f;
    #pragma unroll
    for (int k = 0; k < 3; k++) { float d = x[k] - mu; vs += d * d; }
    float var = blockSum(vs) * (1.0f / ND);
    float rstd = rsqrtf(var + 1e-12f);
    #pragma unroll
    for (int k = 0; k < 3; k++) {
        int c = t + k * 256;
        out[row * ND + c] = (x[k] - mu) * rstd * gamma[c] + beta[c];
    }
}

// ---------------- launch ----------------
extern "C" void kernel_launch(void* const* d_in, const int* in_sizes, int n_in,
                              void* d_out, int out_size)
{
    const float* hidden    = (const float*)d_in[0];
    const float* attn_mask = (const float*)d_in[1];
    const float* head_mask = (const float*)d_in[2];
    const float* Wq = (const float*)d_in[3];
    const float* bq = (const float*)d_in[4];
    const float* Wk = (const float*)d_in[5];
    const float* bk = (const float*)d_in[6];
    const float* Wv = (const float*)d_in[7];
    const float* bv = (const float*)d_in[8];
    const float* Wo = (const float*)d_in[9];
    const float* bo = (const float*)d_in[10];
    const float* gamma = (const float*)d_in[11];
    const float* beta  = (const float*)d_in[12];
    float* out = (float*)d_out;

    void *pq, *pk, *pv, *pc, *pp, *ph, *pw;
    cudaGetSymbolAddress(&pq, g_q);
    cudaGetSymbolAddress(&pk, g_k);
    cudaGetSymbolAddress(&pv, g_v);
    cudaGetSymbolAddress(&pc, g_ctx);
    cudaGetSymbolAddress(&pp, g_proj);
    cudaGetSymbolAddress(&ph, g_hid);
    cudaGetSymbolAddress(&pw, g_wb);
    __nv_bfloat16* q   = (__nv_bfloat16*)pq;
    __nv_bfloat16* k   = (__nv_bfloat16*)pk;
    __nv_bfloat16* v   = (__nv_bfloat16*)pv;
    __nv_bfloat16* cx  = (__nv_bfloat16*)pc;
    float*         pr  = (float*)pp;
    __nv_bfloat16* hb  = (__nv_bfloat16*)ph;
    __nv_bfloat16* wb  = (__nv_bfloat16*)pw;

    const int FLASH_SMEM = 384 * FW * 4 + 4096;   // 59392 B
    const int GEMM_SMEM  = 4 * 128 * BSW * 4;     // 40960 B
    static int attr_set = 0;
    if (!attr_set) {
        cudaFuncSetAttribute(flash_bf16_kernel,
                             cudaFuncAttributeMaxDynamicSharedMemorySize, FLASH_SMEM);
        cudaFuncSetAttribute(bf16_gemm_ca2<true>,
                             cudaFuncAttributeMaxDynamicSharedMemorySize, GEMM_SMEM);
        cudaFuncSetAttribute(bf16_gemm_ca2<false>,
                             cudaFuncAttributeMaxDynamicSharedMemorySize, GEMM_SMEM);
        attr_set = 1;
    }

    // pre-convert hidden + weights to bf16
    cvt_hid_kernel<<<NM * ND / 4 / 256, 256>>>(hidden, hb);
    dim3 gW(WSZ / 4 / 256, 1, 4);   // (576,1,4)
    cvt_w_kernel<<<gW, 256>>>(Wq, Wk, Wv, Wo, wb);

    // fused QKV: q scaled by 0.125*log2e in epilogue (softmax exp2 domain)
    dim3 gQKV(ND / 128, NM / 128, 3);   // (6, 64, 3)
    bf16_gemm_ca2<true><<<gQKV, 256, GEMM_SMEM>>>(
        hb, wb, (long)WSZ, bq, bk, bv, q, k, v, ND, QSCALE, 1.0f, 1.0f);

    dim3 gF(NS / 128, NBH);             // (8, 96)
    flash_bf16_kernel<<<gF, 128, FLASH_SMEM>>>(q, k, v, attn_mask, head_mask, cx);

    dim3 gO(ND / 128, NM / 128, 1);     // (6, 64, 1)
    bf16_gemm_ca2<false><<<gO, 256, GEMM_SMEM>>>(
        cx, wb + 3 * WSZ, 0L, bo, bo, bo, pr, pr, pr, ND, 1.0f, 1.0f, 1.0f);

    ln_kernel<<<NM, 256>>>(pr, hidden, gamma, beta, out);
}

// round 14
// speedup vs baseline: 2.0335x; 1.0362x over previous
#include <cuda_runtime.h>
#include <cuda_bf16.h>
#include <math.h>
#include <stdint.h>

// Problem constants
#define NB 8
#define NS 1024
#define ND 768
#define NH 12
#define NHD 64
#define NM (NB*NS)        // 8192 rows
#define NBH (NB*NH)       // 96 batch-head pairs
#define WSZ (ND*ND)       // 589824

#define LOG2E 1.4426950408889634f
#define QSCALE (0.125f * LOG2E)

// ---------------- scratch (static device globals; no allocation) ----------------
__device__ __nv_bfloat16 g_q  [NM*ND];
__device__ __nv_bfloat16 g_k  [NM*ND];
__device__ __nv_bfloat16 g_v  [NM*ND];
__device__ __nv_bfloat16 g_ctx[NM*ND];
__device__ float         g_proj[NM*ND];
__device__ __nv_bfloat16 g_hid[NM*ND];     // hidden pre-converted to bf16
__device__ __nv_bfloat16 g_wb [4*WSZ];     // Wq|Wk|Wv|Wo pre-converted to bf16

// ---------------- helpers ----------------
__device__ __forceinline__ float warpSum(float v) {
    #pragma unroll
    for (int o = 16; o; o >>= 1) v += __shfl_xor_sync(0xffffffffu, v, o);
    return v;
}
__device__ __forceinline__ float blockSum(float v) {
    __shared__ float s[8];
    __syncthreads();
    v = warpSum(v);
    if ((threadIdx.x & 31) == 0) s[threadIdx.x >> 5] = v;
    __syncthreads();
    if (threadIdx.x == 0) {
        float t = 0.f;
        #pragma unroll
        for (int i = 0; i < 8; i++) t += s[i];
        s[0] = t;
    }
    __syncthreads();
    return s[0];
}

__device__ __forceinline__ void mma_bf16(float d[4], const uint32_t a[4],
                                         const uint32_t b0, const uint32_t b1) {
    asm volatile(
        "mma.sync.aligned.m16n8k16.row.col.f32.bf16.bf16.f32 "
        "{%0,%1,%2,%3}, {%4,%5,%6,%7}, {%8,%9}, {%0,%1,%2,%3};\n"
        : "+f"(d[0]), "+f"(d[1]), "+f"(d[2]), "+f"(d[3])
        : "r"(a[0]), "r"(a[1]), "r"(a[2]), "r"(a[3]),
          "r"(b0), "r"(b1));
}

__device__ __forceinline__ void ldsm_x4(uint32_t r[4], uint32_t saddr) {
    asm volatile("ldmatrix.sync.aligned.m8n8.x4.shared.b16 {%0,%1,%2,%3}, [%4];"
                 : "=r"(r[0]), "=r"(r[1]), "=r"(r[2]), "=r"(r[3]) : "r"(saddr));
}
__device__ __forceinline__ void ldsm_x4_t(uint32_t r[4], uint32_t saddr) {
    asm volatile("ldmatrix.sync.aligned.m8n8.x4.trans.shared.b16 {%0,%1,%2,%3}, [%4];"
                 : "=r"(r[0]), "=r"(r[1]), "=r"(r[2]), "=r"(r[3]) : "r"(saddr));
}

__device__ __forceinline__ uint32_t pack_bf2(float lo, float hi) {
    __nv_bfloat162 p = __floats2bfloat162_rn(lo, hi);   // .x = lo (low halfword)
    return *(uint32_t*)&p;
}

__device__ __forceinline__ float ex2f(float x) {
    float r;
    asm("ex2.approx.ftz.f32 %0, %1;" : "=f"(r) : "f"(x));
    return r;
}

__device__ __forceinline__ void cp_async16(uint32_t smem_dst, const void* gsrc) {
    asm volatile("cp.async.cg.shared.global [%0], [%1], 16;\n"
                 :: "r"(smem_dst), "l"(gsrc));
}
__device__ __forceinline__ void cp_commit() {
    asm volatile("cp.async.commit_group;\n");
}
__device__ __forceinline__ void cp_wait0() {
    asm volatile("cp.async.wait_group 0;\n");
}
__device__ __forceinline__ void cp_wait1() {
    asm volatile("cp.async.wait_group 1;\n");
}

// ---------------- fp32 -> bf16 conversion kernels ----------------
__global__ __launch_bounds__(256)
void cvt_hid_kernel(const float* __restrict__ src, __nv_bfloat16* __restrict__ dst) {
    const long i = ((long)blockIdx.x * 256 + threadIdx.x) * 4;
    float4 v = *(const float4*)(src + i);
    *(uint2*)(dst + i) = make_uint2(pack_bf2(v.x, v.y), pack_bf2(v.z, v.w));
}
__global__ __launch_bounds__(256)
void cvt_w_kernel(const float* __restrict__ W0, const float* __restrict__ W1,
                  const float* __restrict__ W2, const float* __restrict__ W3,
                  __nv_bfloat16* __restrict__ dst) {
    const int z = blockIdx.z;
    const float* src = (z == 0) ? W0 : (z == 1) ? W1 : (z == 2) ? W2 : W3;
    const long i = ((long)blockIdx.x * 256 + threadIdx.x) * 4;
    float4 v = *(const float4*)(src + i);
    *(uint2*)(dst + (long)z * WSZ + i) =
        make_uint2(pack_bf2(v.x, v.y), pack_bf2(v.z, v.w));
}

// ---------------- BF16 GEMM, 3-stage cp.async pipeline ----------------------
// C[M,768] = A[M,768] @ W[N,768]^T + bias, epilogue scale. A,W bf16 in gmem.
// BM=BN=128, BK=32 halves, 256 thr, 8 warps (warp tile 32x64), 3-stage smem.
// Two cp.async groups in flight; exact wait counts (no empty-commit tricks):
//   iter i: [issue s(i+2)] compute s(i) [wait<1> | wait<0> | none] barrier.
#define GK 768
#define BKH 32             // k per stage (halves)
#define NKS (GK/BKH)       // 24 k-steps
#define BSW 20             // smem row stride in 32-bit words
#define ROWB2 80           // smem row stride bytes
#define BUFB2 (128*ROWB2)  // 10240 B per operand per stage

template<bool CBF>
__global__ __launch_bounds__(256, 2)
void bf16_gemm_ca3(const __nv_bfloat16* __restrict__ A,
                   const __nv_bfloat16* __restrict__ Wbase, long wstride,
                   const float* __restrict__ b0, const float* __restrict__ b1,
                   const float* __restrict__ b2,
                   void* __restrict__ C0, void* __restrict__ C1,
                   void* __restrict__ C2, int N,
                   float s0, float s1, float s2)
{
    extern __shared__ uint32_t sm[];
    // layout: A stages [3][128][20w] | B stages [3][128][20w]
    const int z = blockIdx.z;
    const float* bias = (z == 0) ? b0 : (z == 1) ? b1 : b2;
    void* Cout        = (z == 0) ? C0 : (z == 1) ? C1 : C2;
    const float cscale = (z == 0) ? s0 : (z == 1) ? s1 : s2;
    const __nv_bfloat16* W = Wbase + (long)z * wstride;

    const int t     = threadIdx.x;
    const int warp  = t >> 5;
    const int lane  = t & 31;
    const int warpM = warp >> 1;
    const int warpN = warp & 1;
    const int cRow  = blockIdx.y * 128;
    const int cCol  = blockIdx.x * 128;

    const int aRow  = t >> 2;           // 0..63 (2 passes of 64 rows)
    const int aColB = (t & 3) * 16;     // byte col within 64B k-slab

    const char* Ag = (const char*)(A + (long)(cRow + aRow) * GK) + aColB;
    const char* Wg = (const char*)(W + (long)(cCol + aRow) * GK) + aColB;
    const long ROWSTEP = (long)64 * GK * 2;

    const uint32_t sb = (uint32_t)__cvta_generic_to_shared(sm);
    const uint32_t sA = sb + (uint32_t)(aRow * ROWB2 + aColB);
    const uint32_t sBb = sA + 3 * BUFB2;

    // issue stage s (k offset = s-th BKH slab) into buffer s%3
    auto issue = [&](int s) {
        const uint32_t so = (uint32_t)((s % 3) * BUFB2);
        const long gk = (long)s * BKH * 2;
        cp_async16(sA + so,               Ag + gk);
        cp_async16(sA + so + 64 * ROWB2,  Ag + gk + ROWSTEP);
        cp_async16(sBb + so,              Wg + gk);
        cp_async16(sBb + so + 64 * ROWB2, Wg + gk + ROWSTEP);
        cp_commit();
    };

    // prologue: stages 0 and 1 in flight; wait for stage 0
    issue(0);
    issue(1);
    cp_wait1();
    __syncthreads();

    float acc[2][8][4];
    #pragma unroll
    for (int i = 0; i < 2; i++)
        #pragma unroll
        for (int j = 0; j < 8; j++)
            #pragma unroll
            for (int r = 0; r < 4; r++) acc[i][j][r] = 0.f;

    const int lq = lane >> 2;
    const int lr = lane & 3;

    const uint32_t aoff = (uint32_t)((lane & 15) * ROWB2 + ((lane >> 4) << 4));
    const uint32_t boff = (uint32_t)(((lane & 7) + ((lane >> 4) << 3)) * ROWB2
                                     + (((lane >> 3) & 1) << 4));
    const uint32_t aA0 = sb + (uint32_t)(warpM * 32 * ROWB2) + aoff;
    const uint32_t bB0 = sb + 3 * BUFB2 + (uint32_t)(warpN * 64 * ROWB2) + boff;

    for (int i = 0; i < NKS; i++) {
        // buffer (i+2)%3 held stage i-1; its consumption was sealed by the
        // barrier at the end of iteration i-1.
        if (i + 2 < NKS) issue(i + 2);

        const uint32_t bufo = (uint32_t)((i % 3) * BUFB2);
        const uint32_t ab   = aA0 + bufo;
        const uint32_t bb0  = bB0 + bufo;

        #pragma unroll
        for (int kb = 0; kb < 2; kb++) {
            uint32_t a0[4], a1[4];
            ldsm_x4(a0, ab + kb * 32);
            ldsm_x4(a1, ab + 16 * ROWB2 + kb * 32);
            #pragma unroll
            for (int nt2 = 0; nt2 < 4; nt2++) {
                uint32_t bbr[4];
                ldsm_x4(bbr, bb0 + nt2 * (16 * ROWB2) + kb * 32);
                mma_bf16(acc[0][nt2 * 2],     a0, bbr[0], bbr[1]);
                mma_bf16(acc[0][nt2 * 2 + 1], a0, bbr[2], bbr[3]);
                mma_bf16(acc[1][nt2 * 2],     a1, bbr[0], bbr[1]);
                mma_bf16(acc[1][nt2 * 2 + 1], a1, bbr[2], bbr[3]);
            }
        }

        // pending groups: s(i+1) [+ s(i+2) if issued]. Guarantee s(i+1) ready.
        if (i + 2 < NKS)      cp_wait1();
        else if (i + 1 < NKS) cp_wait0();
        __syncthreads();
    }

    // ---- epilogue: (acc + bias) * cscale ----
    #pragma unroll
    for (int nt = 0; nt < 8; nt++) {
        const int col = cCol + warpN * 64 + nt * 8 + lr * 2;
        const float2 bb = *(const float2*)(bias + col);
        #pragma unroll
        for (int mt = 0; mt < 2; mt++) {
            const int row = cRow + warpM * 32 + mt * 16 + lq;
            float c0 = (acc[mt][nt][0] + bb.x) * cscale;
            float c1 = (acc[mt][nt][1] + bb.y) * cscale;
            float c2 = (acc[mt][nt][2] + bb.x) * cscale;
            float c3 = (acc[mt][nt][3] + bb.y) * cscale;
            if (CBF) {
                __nv_bfloat16* Cb = (__nv_bfloat16*)Cout;
                *(uint32_t*)(Cb + (long)row * N + col)       = pack_bf2(c0, c1);
                *(uint32_t*)(Cb + (long)(row + 8) * N + col) = pack_bf2(c2, c3);
            } else {
                float* Cf = (float*)Cout;
                *(float2*)(Cf + (long)row * N + col)       = make_float2(c0, c1);
                *(float2*)(Cf + (long)(row + 8) * N + col) = make_float2(c2, c3);
            }
        }
    }
}

// ---------------- BF16 flash attention (unchanged from round 13) ------------
#define FW 36     // row stride in 32-bit words (72 bf16)
#define ROWB 144  // row stride bytes

__global__ __launch_bounds__(128, 2)
void flash_bf16_kernel(const __nv_bfloat16* __restrict__ Q,
                       const __nv_bfloat16* __restrict__ Kx,
                       const __nv_bfloat16* __restrict__ Vx,
                       const float* __restrict__ mask,
                       const float* __restrict__ head_mask,
                       __nv_bfloat16* __restrict__ Cx)
{
    extern __shared__ uint32_t fsm[];
    float* Ms = (float*)(fsm + 384 * FW);    // [1024] mask row (already *log2e)

    const int bh = blockIdx.y;
    const int b  = bh / NH;
    const int h  = bh % NH;
    const int q0 = blockIdx.x * 128;
    const int t  = threadIdx.x;
    const int warp = t >> 5, lane = t & 31;
    const int lq = lane >> 2, lr = lane & 3;
    const int qrow = warp * 32;

    const __nv_bfloat16* Qg = Q  + (long)b * NS * ND + (long)h * NHD;
    const __nv_bfloat16* Kg = Kx + (long)b * NS * ND + (long)h * NHD;
    const __nv_bfloat16* Vg = Vx + (long)b * NS * ND + (long)h * NHD;

    const uint32_t sb = (uint32_t)__cvta_generic_to_shared(fsm);
    const int seg = t & 7;
    const int rb  = t >> 3;

    {
        #pragma unroll
        for (int i = 0; i < 8; i++) {
            const int r = i * 16 + rb;
            uint4 qv = *(const uint4*)((const char*)(Qg + (long)(q0 + r) * ND) + seg * 16);
            *(uint4*)((char*)fsm + r * ROWB + seg * 16) = qv;
        }
        float4 m0v = *(const float4*)(mask + b * NS + t * 8);
        float4 m1v = *(const float4*)(mask + b * NS + t * 8 + 4);
        m0v.x *= LOG2E; m0v.y *= LOG2E; m0v.z *= LOG2E; m0v.w *= LOG2E;
        m1v.x *= LOG2E; m1v.y *= LOG2E; m1v.z *= LOG2E; m1v.w *= LOG2E;
        *(float4*)&Ms[t * 8]     = m0v;
        *(float4*)&Ms[t * 8 + 4] = m1v;

        #pragma unroll
        for (int i = 0; i < 4; i++) {
            const int r = i * 16 + rb;
            cp_async16(sb + (uint32_t)((128 + r) * ROWB + seg * 16),
                       (const char*)(Kg + (long)r * ND) + seg * 16);
            cp_async16(sb + (uint32_t)((192 + r) * ROWB + seg * 16),
                       (const char*)(Vg + (long)r * ND) + seg * 16);
        }
        cp_commit();
        cp_wait0();
    }
    __syncthreads();

    const uint32_t aoff = (uint32_t)((lane & 15) * ROWB + ((lane >> 4) << 4));
    const uint32_t koff = (uint32_t)(((lane & 7) + ((lane >> 4) << 3)) * ROWB
                                     + (((lane >> 3) & 1) << 4));
    const uint32_t voff = (uint32_t)(((lane & 7) + (((lane >> 3) & 1) << 3)) * ROWB
                                     + ((lane >> 4) << 4));

    const uint32_t qA = sb + (uint32_t)(qrow * ROWB) + aoff;

    uint32_t qf[2][4][4];
    #pragma unroll
    for (int mt = 0; mt < 2; mt++)
        #pragma unroll
        for (int ks = 0; ks < 4; ks++)
            ldsm_x4(qf[mt][ks], qA + mt * (16 * ROWB) + ks * 32);

    float acc_o[2][8][4];
    #pragma unroll
    for (int mt = 0; mt < 2; mt++)
        #pragma unroll
        for (int nt = 0; nt < 8; nt++)
            #pragma unroll
            for (int j = 0; j < 4; j++) acc_o[mt][nt][j] = 0.f;
    float m[4], l[4];
    #pragma unroll
    for (int i = 0; i < 4; i++) { m[i] = -3.4e38f; l[i] = 0.f; }

    int buf = 0;
    for (int it = 0; it < 16; it++) {
        const int k0 = it * 64;
        const bool more = it < 15;

        if (more) {
            const int nbase = 128 + (buf ^ 1) * 128;
            #pragma unroll
            for (int i = 0; i < 4; i++) {
                const int r = i * 16 + rb;
                cp_async16(sb + (uint32_t)((nbase + r) * ROWB + seg * 16),
                           (const char*)(Kg + (long)(k0 + 64 + r) * ND) + seg * 16);
                cp_async16(sb + (uint32_t)((nbase + 64 + r) * ROWB + seg * 16),
                           (const char*)(Vg + (long)(k0 + 64 + r) * ND) + seg * 16);
            }
            cp_commit();
        }

        const uint32_t kB = sb + (uint32_t)((128 + buf * 128) * ROWB) + koff;
        const uint32_t vB = sb + (uint32_t)((192 + buf * 128) * ROWB) + voff;

        float acc_s[2][8][4];
        #pragma unroll
        for (int mt = 0; mt < 2; mt++)
            #pragma unroll
            for (int nt = 0; nt < 8; nt++)
                #pragma unroll
                for (int j = 0; j < 4; j++) acc_s[mt][nt][j] = 0.f;

        #pragma unroll
        for (int ks = 0; ks < 4; ks++) {
            #pragma unroll
            for (int nt2 = 0; nt2 < 4; nt2++) {
                uint32_t bb[4];
                ldsm_x4(bb, kB + nt2 * (16 * ROWB) + ks * 32);
                mma_bf16(acc_s[0][nt2 * 2],     qf[0][ks], bb[0], bb[1]);
                mma_bf16(acc_s[0][nt2 * 2 + 1], qf[0][ks], bb[2], bb[3]);
                mma_bf16(acc_s[1][nt2 * 2],     qf[1][ks], bb[0], bb[1]);
                mma_bf16(acc_s[1][nt2 * 2 + 1], qf[1][ks], bb[2], bb[3]);
            }
        }

        uint32_t pf[2][8][2];
        #pragma unroll
        for (int mt = 0; mt < 2; mt++) {
            float mx0 = -3.4e38f, mx1 = -3.4e38f;
            #pragma unroll
            for (int nt = 0; nt < 8; nt++) {
                float2 mk = *(const float2*)&Ms[k0 + nt * 8 + lr * 2];
                acc_s[mt][nt][0] += mk.x;
                acc_s[mt][nt][1] += mk.y;
                acc_s[mt][nt][2] += mk.x;
                acc_s[mt][nt][3] += mk.y;
                mx0 = fmaxf(mx0, fmaxf(acc_s[mt][nt][0], acc_s[mt][nt][1]));
                mx1 = fmaxf(mx1, fmaxf(acc_s[mt][nt][2], acc_s[mt][nt][3]));
            }
            mx0 = fmaxf(mx0, __shfl_xor_sync(0xffffffffu, mx0, 1));
            mx0 = fmaxf(mx0, __shfl_xor_sync(0xffffffffu, mx0, 2));
            mx1 = fmaxf(mx1, __shfl_xor_sync(0xffffffffu, mx1, 1));
            mx1 = fmaxf(mx1, __shfl_xor_sync(0xffffffffu, mx1, 2));

            const float mn0 = fmaxf(m[mt * 2 + 0], mx0);
            const float mn1 = fmaxf(m[mt * 2 + 1], mx1);
            const float corr0 = ex2f(m[mt * 2 + 0] - mn0);
            const float corr1 = ex2f(m[mt * 2 + 1] - mn1);
            m[mt * 2 + 0] = mn0;
            m[mt * 2 + 1] = mn1;

            float ls0 = 0.f, ls1 = 0.f;
            #pragma unroll
            for (int nt = 0; nt < 8; nt++) {
                __nv_bfloat162 pb0 = __floats2bfloat162_rn(ex2f(acc_s[mt][nt][0] - mn0),
                                                           ex2f(acc_s[mt][nt][1] - mn0));
                __nv_bfloat162 pb1 = __floats2bfloat162_rn(ex2f(acc_s[mt][nt][2] - mn1),
                                                           ex2f(acc_s[mt][nt][3] - mn1));
                ls0 += __bfloat162float(pb0.x) + __bfloat162float(pb0.y);
                ls1 += __bfloat162float(pb1.x) + __bfloat162float(pb1.y);
                pf[mt][nt][0] = *(uint32_t*)&pb0;
                pf[mt][nt][1] = *(uint32_t*)&pb1;
            }
            ls0 += __shfl_xor_sync(0xffffffffu, ls0, 1);
            ls0 += __shfl_xor_sync(0xffffffffu, ls0, 2);
            ls1 += __shfl_xor_sync(0xffffffffu, ls1, 1);
            ls1 += __shfl_xor_sync(0xffffffffu, ls1, 2);
            l[mt * 2 + 0] = l[mt * 2 + 0] * corr0 + ls0;
            l[mt * 2 + 1] = l[mt * 2 + 1] * corr1 + ls1;

            #pragma unroll
            for (int nt = 0; nt < 8; nt++) {
                acc_o[mt][nt][0] *= corr0;
                acc_o[mt][nt][1] *= corr0;
                acc_o[mt][nt][2] *= corr1;
                acc_o[mt][nt][3] *= corr1;
            }
        }

        #pragma unroll
        for (int kb = 0; kb < 4; kb++) {
            uint32_t a0[4] = {pf[0][2*kb][0], pf[0][2*kb][1],
                              pf[0][2*kb+1][0], pf[0][2*kb+1][1]};
            uint32_t a1[4] = {pf[1][2*kb][0], pf[1][2*kb][1],
                              pf[1][2*kb+1][0], pf[1][2*kb+1][1]};
            #pragma unroll
            for (int nd2 = 0; nd2 < 4; nd2++) {
                uint32_t bb[4];
                ldsm_x4_t(bb, vB + kb * (16 * ROWB) + nd2 * 32);
                mma_bf16(acc_o[0][nd2 * 2],     a0, bb[0], bb[1]);
                mma_bf16(acc_o[0][nd2 * 2 + 1], a0, bb[2], bb[3]);
                mma_bf16(acc_o[1][nd2 * 2],     a1, bb[0], bb[1]);
                mma_bf16(acc_o[1][nd2 * 2 + 1], a1, bb[2], bb[3]);
            }
        }

        if (more) cp_wait0();
        __syncthreads();
        buf ^= 1;
    }

    const float hm = head_mask[h];
    #pragma unroll
    for (int mt = 0; mt < 2; mt++) {
        const float inv0 = hm / l[mt * 2 + 0];
        const float inv1 = hm / l[mt * 2 + 1];
        #pragma unroll
        for (int nt = 0; nt < 8; nt++) {
            const int col = h * NHD + nt * 8 + lr * 2;
            const long r0 = (long)b * NS + q0 + qrow + mt * 16 + lq;
            *(uint32_t*)(Cx + r0 * ND + col) =
                pack_bf2(acc_o[mt][nt][0] * inv0, acc_o[mt][nt][1] * inv0);
            *(uint32_t*)(Cx + (r0 + 8) * ND + col) =
                pack_bf2(acc_o[mt][nt][2] * inv1, acc_o[mt][nt][3] * inv1);
        }
    }
}

// ---------------- residual + LayerNorm ----------------
__global__ __launch_bounds__(256)
void ln_kernel(const float* __restrict__ proj, const float* __restrict__ hidden,
               const float* __restrict__ gamma, const float* __restrict__ beta,
               float* __restrict__ out)
{
    const long row = blockIdx.x;
    const int t = threadIdx.x;
    float x[3];
    #pragma unroll
    for (int k = 0; k < 3; k++) {
        long idx = row * ND + t + k * 256;
        x[k] = proj[idx] + hidden[idx];
    }
    float s = x[0] + x[1] + x[2];
    float mu = blockSum(s) * (1.0f / ND);
    float vs = 0.f;
    #pragma unroll
    for (int k = 0; k < 3; k++) { float d = x[k] - mu; vs += d * d; }
    float var = blockSum(vs) * (1.0f / ND);
    float rstd = rsqrtf(var + 1e-12f);
    #pragma unroll
    for (int k = 0; k < 3; k++) {
        int c = t + k * 256;
        out[row * ND + c] = (x[k] - mu) * rstd * gamma[c] + beta[c];
    }
}

// ---------------- launch ----------------
extern "C" void kernel_launch(void* const* d_in, const int* in_sizes, int n_in,
                              void* d_out, int out_size)
{
    const float* hidden    = (const float*)d_in[0];
    const float* attn_mask = (const float*)d_in[1];
    const float* head_mask = (const float*)d_in[2];
    const float* Wq = (const float*)d_in[3];
    const float* bq = (const float*)d_in[4];
    const float* Wk = (const float*)d_in[5];
    const float* bk = (const float*)d_in[6];
    const float* Wv = (const float*)d_in[7];
    const float* bv = (const float*)d_in[8];
    const float* Wo = (const float*)d_in[9];
    const float* bo = (const float*)d_in[10];
    const float* gamma = (const float*)d_in[11];
    const float* beta  = (const float*)d_in[12];
    float* out = (float*)d_out;

    void *pq, *pk, *pv, *pc, *pp, *ph, *pw;
    cudaGetSymbolAddress(&pq, g_q);
    cudaGetSymbolAddress(&pk, g_k);
    cudaGetSymbolAddress(&pv, g_v);
    cudaGetSymbolAddress(&pc, g_ctx);
    cudaGetSymbolAddress(&pp, g_proj);
    cudaGetSymbolAddress(&ph, g_hid);
    cudaGetSymbolAddress(&pw, g_wb);
    __nv_bfloat16* q   = (__nv_bfloat16*)pq;
    __nv_bfloat16* k   = (__nv_bfloat16*)pk;
    __nv_bfloat16* v   = (__nv_bfloat16*)pv;
    __nv_bfloat16* cx  = (__nv_bfloat16*)pc;
    float*         pr  = (float*)pp;
    __nv_bfloat16* hb  = (__nv_bfloat16*)ph;
    __nv_bfloat16* wb  = (__nv_bfloat16*)pw;

    const int FLASH_SMEM = 384 * FW * 4 + 4096;   // 59392 B
    const int GEMM_SMEM  = 2 * 3 * BUFB2;         // 61440 B
    static int attr_set = 0;
    if (!attr_set) {
        cudaFuncSetAttribute(flash_bf16_kernel,
                             cudaFuncAttributeMaxDynamicSharedMemorySize, FLASH_SMEM);
        cudaFuncSetAttribute(bf16_gemm_ca3<true>,
                             cudaFuncAttributeMaxDynamicSharedMemorySize, GEMM_SMEM);
        cudaFuncSetAttribute(bf16_gemm_ca3<false>,
                             cudaFuncAttributeMaxDynamicSharedMemorySize, GEMM_SMEM);
        attr_set = 1;
    }

    // pre-convert hidden + weights to bf16
    cvt_hid_kernel<<<NM * ND / 4 / 256, 256>>>(hidden, hb);
    dim3 gW(WSZ / 4 / 256, 1, 4);   // (576,1,4)
    cvt_w_kernel<<<gW, 256>>>(Wq, Wk, Wv, Wo, wb);

    // fused QKV: q scaled by 0.125*log2e in epilogue (softmax exp2 domain)
    dim3 gQKV(ND / 128, NM / 128, 3);   // (6, 64, 3)
    bf16_gemm_ca3<true><<<gQKV, 256, GEMM_SMEM>>>(
        hb, wb, (long)WSZ, bq, bk, bv, q, k, v, ND, QSCALE, 1.0f, 1.0f);

    dim3 gF(NS / 128, NBH);             // (8, 96)
    flash_bf16_kernel<<<gF, 128, FLASH_SMEM>>>(q, k, v, attn_mask, head_mask, cx);

    dim3 gO(ND / 128, NM / 128, 1);     // (6, 64, 1)
    bf16_gemm_ca3<false><<<gO, 256, GEMM_SMEM>>>(
        cx, wb + 3 * WSZ, 0L, bo, bo, bo, pr, pr, pr, ND, 1.0f, 1.0f, 1.0f);

    ln_kernel<<<NM, 256>>>(pr, hidden, gamma, beta, out);
}